// round 2
// baseline (speedup 1.0000x reference)
#include <cuda_runtime.h>
#include <math.h>

#define HN   12
#define TT   1024
#define DD   64
#define DINE 768
#define NBB  4
#define NTR  (NBB*TT)   // 4096 rows

#define SPAD 1026       // sS row stride
#define KPAD 65         // sQ/sK row stride

// Scratch (static device globals — allocation-free)
__device__ float g_q[NBB*HN*TT*DD];
__device__ float g_k[NBB*HN*TT*DD];
__device__ float g_v[NBB*HN*TT*DD];
__device__ float g_o[NTR*DINE];

// ---------------------------------------------------------------------------
// QKV projection as one logical GEMM: C[4096, 36*64] = X[4096,768] @ Wcat
// blockIdx.x: 128-row tile (32); blockIdx.y: 128-col tile (18) = (mat, head pair)
// 256 threads, 8x8 microtile.
// ---------------------------------------------------------------------------
__global__ __launch_bounds__(256) void qkv_kernel(
    const float* __restrict__ x,
    const float* __restrict__ Wq, const float* __restrict__ Wk,
    const float* __restrict__ Wv)
{
    int cb  = blockIdx.y;
    int mat = cb / 6, hp = cb % 6;
    int h0  = 2 * hp;
    const float* Wm = (mat == 0 ? Wq : mat == 1 ? Wk : Wv);
    float* outp     = (mat == 0 ? g_q : mat == 1 ? g_k : g_v);
    int row0 = blockIdx.x * 128;

    __shared__ float sA[16][128];  // A transposed: [kk][row]
    __shared__ float sB[16][128];  // [kk][col]  col = (head offset, d)

    int tid = threadIdx.x;
    int tx = tid & 15, ty = tid >> 4;

    float acc[8][8];
#pragma unroll
    for (int i = 0; i < 8; i++)
#pragma unroll
        for (int j = 0; j < 8; j++) acc[i][j] = 0.f;

    for (int k0 = 0; k0 < DINE; k0 += 16) {
#pragma unroll
        for (int i = 0; i < 2; i++) {              // A: 128x16 = 512 float4
            int v = tid + 256 * i;
            int r = v >> 2, kq = v & 3;
            float4 a = *(const float4*)&x[(size_t)(row0 + r) * DINE + k0 + 4 * kq];
            sA[4*kq+0][r] = a.x; sA[4*kq+1][r] = a.y;
            sA[4*kq+2][r] = a.z; sA[4*kq+3][r] = a.w;
        }
#pragma unroll
        for (int i = 0; i < 2; i++) {              // B: 16x128 = 512 float4
            int v = tid + 256 * i;
            int kk = v >> 5, c4 = v & 31;
            int h = h0 + (c4 >> 4);
            int d = 4 * (c4 & 15);
            *(float4*)&sB[kk][4*c4] =
                *(const float4*)&Wm[((size_t)h * DINE + (k0 + kk)) * DD + d];
        }
        __syncthreads();
#pragma unroll
        for (int kk = 0; kk < 16; kk++) {
            float4 a0 = *(float4*)&sA[kk][ty*8];
            float4 a1 = *(float4*)&sA[kk][ty*8+4];
            float4 b0 = *(float4*)&sB[kk][tx*8];
            float4 b1 = *(float4*)&sB[kk][tx*8+4];
            float av[8] = {a0.x,a0.y,a0.z,a0.w,a1.x,a1.y,a1.z,a1.w};
            float bv[8] = {b0.x,b0.y,b0.z,b0.w,b1.x,b1.y,b1.z,b1.w};
#pragma unroll
            for (int i = 0; i < 8; i++)
#pragma unroll
                for (int j = 0; j < 8; j++)
                    acc[i][j] = fmaf(av[i], bv[j], acc[i][j]);
        }
        __syncthreads();
    }
    // Epilogue: thread covers 8 rows x 8 cols; the 8 cols lie inside one head.
    int h = h0 + (tx >> 3);
    int d0 = (tx * 8) & 63;
#pragma unroll
    for (int i = 0; i < 8; i++) {
        int row = row0 + ty*8 + i;
        int n = row >> 10, t = row & (TT - 1);
        float* dst = &outp[(size_t)((n*HN + h)*TT + t)*DD + d0];
        *(float4*)&dst[0] = make_float4(acc[i][0], acc[i][1], acc[i][2], acc[i][3]);
        *(float4*)&dst[4] = make_float4(acc[i][4], acc[i][5], acc[i][6], acc[i][7]);
    }
}

// ---------------------------------------------------------------------------
// Fused attention: per block (n,h, 32-query tile).
// ---------------------------------------------------------------------------
__global__ __launch_bounds__(256) void attn_kernel(float* __restrict__ attn_out)
{
    extern __shared__ float sm[];
    float* sS = sm;                     // 32 * SPAD
    float* sQ = sm + 32 * SPAD;         // 32 * KPAD
    float* sK = sQ + 32 * KPAD;         // 256 * KPAD (reused for V)

    int qt = gridDim.x - 1 - blockIdx.x;   // heavy tiles first
    int bh = blockIdx.y;
    int tq0 = qt * 32;
    const float* qp = g_q + (size_t)bh * TT * DD;
    const float* kp = g_k + (size_t)bh * TT * DD;
    const float* vp = g_v + (size_t)bh * TT * DD;

    int tid = threadIdx.x, lane = tid & 31, warp = tid >> 5;
    int kmax = tq0 + 32;

    // Load Q tile [32 x 64]
#pragma unroll
    for (int i = 0; i < 2; i++) {
        int v = tid + 256 * i;
        int r = v >> 4, e4 = v & 15;
        float4 q4 = *(const float4*)&qp[(size_t)(tq0 + r) * DD + 4 * e4];
        float* dst = &sQ[r * KPAD + 4 * e4];
        dst[0] = q4.x; dst[1] = q4.y; dst[2] = q4.z; dst[3] = q4.w;
    }
    __syncthreads();

    // ---- S = Q @ K^T over needed key blocks (causal skip) ----
    int nkb = (kmax + 255) >> 8;
    for (int kb = 0; kb < nkb; kb++) {
#pragma unroll
        for (int i = 0; i < 16; i++) {            // 256x64 keys
            int v = tid + 256 * i;
            int s = v >> 4, e4 = v & 15;
            float4 k4 = *(const float4*)&kp[(size_t)(kb*256 + s) * DD + 4 * e4];
            float* dst = &sK[s * KPAD + 4 * e4];
            dst[0] = k4.x; dst[1] = k4.y; dst[2] = k4.z; dst[3] = k4.w;
        }
        __syncthreads();

        float acc[4][8];
#pragma unroll
        for (int i = 0; i < 4; i++)
#pragma unroll
            for (int j = 0; j < 8; j++) acc[i][j] = 0.f;

#pragma unroll 4
        for (int e = 0; e < 64; e++) {
            float a[4], b[8];
#pragma unroll
            for (int i = 0; i < 4; i++) a[i] = sQ[(warp*4 + i) * KPAD + e];
#pragma unroll
            for (int j = 0; j < 8; j++) b[j] = sK[(lane + 32*j) * KPAD + e];
#pragma unroll
            for (int i = 0; i < 4; i++)
#pragma unroll
                for (int j = 0; j < 8; j++)
                    acc[i][j] = fmaf(a[i], b[j], acc[i][j]);
        }
#pragma unroll
        for (int i = 0; i < 4; i++)
#pragma unroll
            for (int j = 0; j < 8; j++)
                sS[(warp*4 + i) * SPAD + kb*256 + lane + 32*j] = acc[i][j];
        __syncthreads();
    }

    // ---- mask + softmax (each warp owns its 4 rows; only s <= tq is live) ----
#pragma unroll
    for (int i = 0; i < 4; i++) {
        int r = warp*4 + i, tq = tq0 + r;
        float* row = &sS[r * SPAD];
        int len = tq + 1;
        float mx = -INFINITY;
        for (int s = lane; s < len; s += 32) {
            float vv = row[s];
            if (vv == 0.0f) vv = -INFINITY;   // faithful "tril zeros -> -inf" quirk
            row[s] = vv;
            mx = fmaxf(mx, vv);
        }
#pragma unroll
        for (int o = 16; o > 0; o >>= 1) mx = fmaxf(mx, __shfl_xor_sync(0xffffffffu, mx, o));
        float sum = 0.f;
        for (int s = lane; s < len; s += 32) {
            float p = __expf(row[s] - mx);
            row[s] = p;
            sum += p;
        }
#pragma unroll
        for (int o = 16; o > 0; o >>= 1) sum += __shfl_xor_sync(0xffffffffu, sum, o);
        float inv = 1.f / sum;

        if (attn_out) {
            float* arow = attn_out + ((size_t)bh * TT + tq) * TT;
            for (int s = lane; s < len; s += 32) {
                float p = row[s] * inv;
                row[s] = p;
                arow[s] = p;
            }
            for (int s = len + lane; s < TT; s += 32) arow[s] = 0.0f;
        } else {
            for (int s = lane; s < len; s += 32) row[s] *= inv;
        }
        // zero dead region read by PV (cols in [len, kmax))
        for (int s = len + lane; s < kmax; s += 32) row[s] = 0.0f;
    }

    // ---- O = P @ V (keys < kmax) ----
    float oacc[4][2];
#pragma unroll
    for (int i = 0; i < 4; i++) { oacc[i][0] = 0.f; oacc[i][1] = 0.f; }
    for (int sb = 0; sb < kmax; sb += 256) {
        __syncthreads();                           // sK free to overwrite
#pragma unroll
        for (int i = 0; i < 16; i++) {
            int v = tid + 256 * i;
            int s = v >> 4, e4 = v & 15;
            float4 v4 = *(const float4*)&vp[(size_t)(sb + s) * DD + 4 * e4];
            float* dst = &sK[s * KPAD + 4 * e4];
            dst[0] = v4.x; dst[1] = v4.y; dst[2] = v4.z; dst[3] = v4.w;
        }
        __syncthreads();
        int send = min(256, kmax - sb);
#pragma unroll 2
        for (int ss = 0; ss < send; ss += 2) {
            float b00 = sK[ss * KPAD + lane];
            float b01 = sK[ss * KPAD + lane + 32];
            float b10 = sK[(ss+1) * KPAD + lane];
            float b11 = sK[(ss+1) * KPAD + lane + 32];
#pragma unroll
            for (int i = 0; i < 4; i++) {
                float2 a2 = *(float2*)&sS[(warp*4 + i) * SPAD + sb + ss];
                oacc[i][0] = fmaf(a2.x, b00, oacc[i][0]);
                oacc[i][0] = fmaf(a2.y, b10, oacc[i][0]);
                oacc[i][1] = fmaf(a2.x, b01, oacc[i][1]);
                oacc[i][1] = fmaf(a2.y, b11, oacc[i][1]);
            }
        }
    }
    int n = bh / HN, h = bh % HN;
#pragma unroll
    for (int i = 0; i < 4; i++) {
        int t = tq0 + warp*4 + i;
        float* dst = &g_o[(size_t)(n*TT + t) * DINE + h*DD];
        dst[lane]      = oacc[i][0];
        dst[lane + 32] = oacc[i][1];
    }
}

// ---------------------------------------------------------------------------
// Output projection: out[4096,64] = g_o[4096,768] @ Wo[768,64] + bo
// ---------------------------------------------------------------------------
__global__ __launch_bounds__(256) void oproj_kernel(
    const float* __restrict__ Wo, const float* __restrict__ bo,
    float* __restrict__ out)
{
    int row0 = blockIdx.x * 64;
    __shared__ float sA[16][64];
    __shared__ float sB[16][64];
    int tid = threadIdx.x, tx = tid & 15, ty = tid >> 4;

    float acc[4][4];
#pragma unroll
    for (int i = 0; i < 4; i++)
#pragma unroll
        for (int j = 0; j < 4; j++) acc[i][j] = 0.f;

    for (int k0 = 0; k0 < DINE; k0 += 16) {
        {
            int r = tid >> 2, kq = tid & 3;
            float4 a = *(const float4*)&g_o[(size_t)(row0 + r) * DINE + k0 + 4 * kq];
            sA[4*kq+0][r] = a.x; sA[4*kq+1][r] = a.y;
            sA[4*kq+2][r] = a.z; sA[4*kq+3][r] = a.w;
        }
        {
            int kk = tid >> 4, c4 = tid & 15;
            *(float4*)&sB[kk][4*c4] = *(const float4*)&Wo[(size_t)(k0+kk)*DD + 4*c4];
        }
        __syncthreads();
#pragma unroll
        for (int kk = 0; kk < 16; kk++) {
            float4 a = *(float4*)&sA[kk][ty*4];
            float4 b = *(float4*)&sB[kk][tx*4];
            float av[4] = {a.x,a.y,a.z,a.w};
            float bv[4] = {b.x,b.y,b.z,b.w};
#pragma unroll
            for (int i = 0; i < 4; i++)
#pragma unroll
                for (int j = 0; j < 4; j++)
                    acc[i][j] = fmaf(av[i], bv[j], acc[i][j]);
        }
        __syncthreads();
    }
    float4 bias = *(const float4*)&bo[tx*4];
    float bv[4] = {bias.x, bias.y, bias.z, bias.w};
#pragma unroll
    for (int i = 0; i < 4; i++) {
        int row = row0 + ty*4 + i;
        float4 v = make_float4(acc[i][0]+bv[0], acc[i][1]+bv[1],
                               acc[i][2]+bv[2], acc[i][3]+bv[3]);
        *(float4*)&out[(size_t)row * DD + tx*4] = v;
    }
}

// ---------------------------------------------------------------------------
extern "C" void kernel_launch(void* const* d_in, const int* in_sizes, int n_in,
                              void* d_out, int out_size)
{
    const float* x  = (const float*)d_in[0];
    const float* Wq = (const float*)d_in[1];
    const float* Wk = (const float*)d_in[2];
    const float* Wv = (const float*)d_in[3];
    const float* Wo = (const float*)d_in[4];
    const float* bo = (const float*)d_in[5];
    float* out = (float*)d_out;

    const long NTD = (long)NBB * TT * DD;            // 262144
    const long ATT = (long)NBB * HN * TT * TT;       // 50331648
    float* attn = nullptr;
    if ((long)out_size >= NTD + ATT) attn = out + NTD;

    int smem = (32 * SPAD + 32 * KPAD + 256 * KPAD) * (int)sizeof(float); // 206208 B
    cudaFuncSetAttribute(attn_kernel, cudaFuncAttributeMaxDynamicSharedMemorySize, smem);

    qkv_kernel<<<dim3(32, 18), 256>>>(x, Wq, Wk, Wv);
    attn_kernel<<<dim3(32, 48), 256, smem>>>(attn);
    oproj_kernel<<<64, 256>>>(Wo, bo, out);
}

// round 4
// speedup vs baseline: 1.0047x; 1.0047x over previous
#include <cuda_runtime.h>
#include <math.h>

#define HN   12
#define TT   1024
#define DD   64
#define DINE 768
#define NBB  4
#define NTR  (NBB*TT)   // 4096 rows
#define NBH  (NBB*HN)   // 48

// Scratch (static device globals — allocation-free)
__device__ float g_q[NBB*HN*TT*DD];
__device__ float g_k[NBB*HN*TT*DD];
__device__ float g_v[NBB*HN*TT*DD];
__device__ float g_o[NTR*DINE];

// Fast exp on the FMA pipe (avoids MUFU throughput wall). x <= 0 expected.
__device__ __forceinline__ float fexp(float x) {
    x = fmaxf(x, -87.0f);                       // handles -inf
    float y = x * 1.44269504088896f;            // log2(e)
    int   n = __float2int_rn(y);
    float f = y - (float)n;                     // f in [-0.5, 0.5]
    float p = 1.53989348e-4f;                   // 2^f Taylor (ln2^k/k!)
    p = fmaf(p, f, 1.33336246e-3f);
    p = fmaf(p, f, 9.61812910e-3f);
    p = fmaf(p, f, 5.55041087e-2f);
    p = fmaf(p, f, 2.40226507e-1f);
    p = fmaf(p, f, 6.93147181e-1f);
    p = fmaf(p, f, 1.0f);
    float scale = __int_as_float((n + 127) << 23);
    return p * scale;
}

// ---------------------------------------------------------------------------
// QKV projection as one logical GEMM: C[4096, 36*64] = X[4096,768] @ Wcat
// ---------------------------------------------------------------------------
__global__ __launch_bounds__(256) void qkv_kernel(
    const float* __restrict__ x,
    const float* __restrict__ Wq, const float* __restrict__ Wk,
    const float* __restrict__ Wv)
{
    int cb  = blockIdx.y;
    int mat = cb / 6, hp = cb % 6;
    int h0  = 2 * hp;
    const float* Wm = (mat == 0 ? Wq : mat == 1 ? Wk : Wv);
    float* outp     = (mat == 0 ? g_q : mat == 1 ? g_k : g_v);
    int row0 = blockIdx.x * 128;

    __shared__ float sA[16][128];
    __shared__ float sB[16][128];

    int tid = threadIdx.x;
    int tx = tid & 15, ty = tid >> 4;

    float acc[8][8];
#pragma unroll
    for (int i = 0; i < 8; i++)
#pragma unroll
        for (int j = 0; j < 8; j++) acc[i][j] = 0.f;

    for (int k0 = 0; k0 < DINE; k0 += 16) {
#pragma unroll
        for (int i = 0; i < 2; i++) {
            int v = tid + 256 * i;
            int r = v >> 2, kq = v & 3;
            float4 a = *(const float4*)&x[(size_t)(row0 + r) * DINE + k0 + 4 * kq];
            sA[4*kq+0][r] = a.x; sA[4*kq+1][r] = a.y;
            sA[4*kq+2][r] = a.z; sA[4*kq+3][r] = a.w;
        }
#pragma unroll
        for (int i = 0; i < 2; i++) {
            int v = tid + 256 * i;
            int kk = v >> 5, c4 = v & 31;
            int h = h0 + (c4 >> 4);
            int d = 4 * (c4 & 15);
            *(float4*)&sB[kk][4*c4] =
                *(const float4*)&Wm[((size_t)h * DINE + (k0 + kk)) * DD + d];
        }
        __syncthreads();
#pragma unroll
        for (int kk = 0; kk < 16; kk++) {
            float4 a0 = *(float4*)&sA[kk][ty*8];
            float4 a1 = *(float4*)&sA[kk][ty*8+4];
            float4 b0 = *(float4*)&sB[kk][tx*8];
            float4 b1 = *(float4*)&sB[kk][tx*8+4];
            float av[8] = {a0.x,a0.y,a0.z,a0.w,a1.x,a1.y,a1.z,a1.w};
            float bv[8] = {b0.x,b0.y,b0.z,b0.w,b1.x,b1.y,b1.z,b1.w};
#pragma unroll
            for (int i = 0; i < 8; i++)
#pragma unroll
                for (int j = 0; j < 8; j++)
                    acc[i][j] = fmaf(av[i], bv[j], acc[i][j]);
        }
        __syncthreads();
    }
    int h = h0 + (tx >> 3);
    int d0 = (tx * 8) & 63;
#pragma unroll
    for (int i = 0; i < 8; i++) {
        int row = row0 + ty*8 + i;
        int n = row >> 10, t = row & (TT - 1);
        float* dst = &outp[(size_t)((n*HN + h)*TT + t)*DD + d0];
        *(float4*)&dst[0] = make_float4(acc[i][0], acc[i][1], acc[i][2], acc[i][3]);
        *(float4*)&dst[4] = make_float4(acc[i][4], acc[i][5], acc[i][6], acc[i][7]);
    }
}

// ---------------------------------------------------------------------------
// S = Q @ K^T, per (bh, lower-triangle 128x128 block). Raw scores -> attn buf.
// ---------------------------------------------------------------------------
#define QSTR 132   // multiple of 4 (float4-aligned), not multiple of 32
__global__ __launch_bounds__(256) void sgemm_kernel(float* __restrict__ attn)
{
    extern __shared__ float sm[];
    float* sQt = sm;                 // [64][QSTR]
    float* sKt = sm + 64 * QSTR;     // [64][QSTR]

    // triangular block enumeration
    int idx = blockIdx.x, rb = 0;
    while (idx > rb) { idx -= rb + 1; rb++; }
    int cb = idx;
    int bh = blockIdx.y;

    const float* qp = g_q + (size_t)bh * TT * DD + (size_t)rb * 128 * DD;
    const float* kp = g_k + (size_t)bh * TT * DD + (size_t)cb * 128 * DD;

    int tid = threadIdx.x;
    int tx = tid & 15, ty = tid >> 4;

#pragma unroll
    for (int i = 0; i < 8; i++) {                 // load+transpose Q,K tiles
        int v = tid + 256 * i;
        int r = v >> 4, e4 = v & 15;
        float4 q = *(const float4*)&qp[(size_t)r * DD + 4 * e4];
        sQt[(4*e4+0)*QSTR + r] = q.x; sQt[(4*e4+1)*QSTR + r] = q.y;
        sQt[(4*e4+2)*QSTR + r] = q.z; sQt[(4*e4+3)*QSTR + r] = q.w;
        float4 k = *(const float4*)&kp[(size_t)r * DD + 4 * e4];
        sKt[(4*e4+0)*QSTR + r] = k.x; sKt[(4*e4+1)*QSTR + r] = k.y;
        sKt[(4*e4+2)*QSTR + r] = k.z; sKt[(4*e4+3)*QSTR + r] = k.w;
    }
    __syncthreads();

    float acc[8][8];
#pragma unroll
    for (int i = 0; i < 8; i++)
#pragma unroll
        for (int j = 0; j < 8; j++) acc[i][j] = 0.f;

#pragma unroll 4
    for (int e = 0; e < 64; e++) {
        float4 a0 = *(float4*)&sQt[e*QSTR + ty*8];
        float4 a1 = *(float4*)&sQt[e*QSTR + ty*8 + 4];
        float4 b0 = *(float4*)&sKt[e*QSTR + tx*8];
        float4 b1 = *(float4*)&sKt[e*QSTR + tx*8 + 4];
        float av[8] = {a0.x,a0.y,a0.z,a0.w,a1.x,a1.y,a1.z,a1.w};
        float bv[8] = {b0.x,b0.y,b0.z,b0.w,b1.x,b1.y,b1.z,b1.w};
#pragma unroll
        for (int i = 0; i < 8; i++)
#pragma unroll
            for (int j = 0; j < 8; j++)
                acc[i][j] = fmaf(av[i], bv[j], acc[i][j]);
    }

#pragma unroll
    for (int i = 0; i < 8; i++) {
        int row = rb*128 + ty*8 + i;
        float* dst = &attn[((size_t)bh * TT + row) * TT + cb*128 + tx*8];
        *(float4*)&dst[0] = make_float4(acc[i][0], acc[i][1], acc[i][2], acc[i][3]);
        *(float4*)&dst[4] = make_float4(acc[i][4], acc[i][5], acc[i][6], acc[i][7]);
    }
}

// ---------------------------------------------------------------------------
// Softmax (causal + "==0 -> -inf" quirk), one warp per row, row in registers.
// ---------------------------------------------------------------------------
__global__ __launch_bounds__(256) void softmax_kernel(float* __restrict__ attn)
{
    int tid = threadIdx.x, lane = tid & 31, warp = tid >> 5;
    int tq = blockIdx.x * 8 + warp;
    int bh = blockIdx.y;
    float* row = attn + ((size_t)bh * TT + tq) * TT;
    int len = tq + 1;

    float pv[32];
    float mx = -INFINITY;
#pragma unroll
    for (int k = 0; k < 32; k++) {
        int s = lane + 32 * k;
        if (s < len) {
            float v = row[s];
            pv[k] = (v == 0.0f) ? -INFINITY : v;
            mx = fmaxf(mx, pv[k]);
        } else pv[k] = -INFINITY;
    }
#pragma unroll
    for (int o = 16; o > 0; o >>= 1) mx = fmaxf(mx, __shfl_xor_sync(0xffffffffu, mx, o));

    float sum = 0.f;
#pragma unroll
    for (int k = 0; k < 32; k++) {
        int s = lane + 32 * k;
        if (s < len) { pv[k] = fexp(pv[k] - mx); sum += pv[k]; }
        else pv[k] = 0.f;
    }
#pragma unroll
    for (int o = 16; o > 0; o >>= 1) sum += __shfl_xor_sync(0xffffffffu, sum, o);
    float inv = 1.f / sum;

#pragma unroll
    for (int k = 0; k < 32; k++) {
        int s = lane + 32 * k;
        row[s] = pv[k] * inv;   // dead region writes 0
    }
}

// ---------------------------------------------------------------------------
// O = P @ V, per (bh, 128-row block). P streamed from attn buf, V via smem.
// 128 threads, 8x8 microtile.
// ---------------------------------------------------------------------------
#define PSTR 132   // multiple of 4, not multiple of 32
#define VSTR 68    // multiple of 4, not multiple of 32
__global__ __launch_bounds__(128) void pv_kernel(const float* __restrict__ attn)
{
    __shared__ float sPt[32 * PSTR];   // [s][row]
    __shared__ float sV [32 * VSTR];   // [s][d]

    int rb = 7 - blockIdx.x;           // heavy tiles first
    int bh = blockIdx.y;
    int row0 = rb * 128;
    int kmax = (rb + 1) * 128;
    const float* vp = g_v + (size_t)bh * TT * DD;
    const float* pp = attn + ((size_t)bh * TT + row0) * TT;

    int tid = threadIdx.x;
    int tx = tid & 7, ty = tid >> 3;

    float acc[8][8];
#pragma unroll
    for (int i = 0; i < 8; i++)
#pragma unroll
        for (int j = 0; j < 8; j++) acc[i][j] = 0.f;

    for (int sb = 0; sb < kmax; sb += 32) {
#pragma unroll
        for (int i = 0; i < 8; i++) {              // P chunk 128x32, transposed
            int v = tid + 128 * i;
            int r = v >> 3, e4 = v & 7;
            float4 p = *(const float4*)&pp[(size_t)r * TT + sb + 4 * e4];
            sPt[(4*e4+0)*PSTR + r] = p.x; sPt[(4*e4+1)*PSTR + r] = p.y;
            sPt[(4*e4+2)*PSTR + r] = p.z; sPt[(4*e4+3)*PSTR + r] = p.w;
        }
#pragma unroll
        for (int i = 0; i < 4; i++) {              // V chunk 32x64
            int v = tid + 128 * i;
            int s = v >> 4, c4 = v & 15;
            *(float4*)&sV[s * VSTR + 4 * c4] =
                *(const float4*)&vp[(size_t)(sb + s) * DD + 4 * c4];
        }
        __syncthreads();
#pragma unroll 4
        for (int s = 0; s < 32; s++) {
            float4 a0 = *(float4*)&sPt[s*PSTR + ty*8];
            float4 a1 = *(float4*)&sPt[s*PSTR + ty*8 + 4];
            float4 b0 = *(float4*)&sV[s*VSTR + tx*8];
            float4 b1 = *(float4*)&sV[s*VSTR + tx*8 + 4];
            float av[8] = {a0.x,a0.y,a0.z,a0.w,a1.x,a1.y,a1.z,a1.w};
            float bv[8] = {b0.x,b0.y,b0.z,b0.w,b1.x,b1.y,b1.z,b1.w};
#pragma unroll
            for (int i = 0; i < 8; i++)
#pragma unroll
                for (int j = 0; j < 8; j++)
                    acc[i][j] = fmaf(av[i], bv[j], acc[i][j]);
        }
        __syncthreads();
    }

    int n = bh / HN, h = bh % HN;
#pragma unroll
    for (int i = 0; i < 8; i++) {
        int t = row0 + ty*8 + i;
        float* dst = &g_o[(size_t)(n*TT + t) * DINE + h*DD + tx*8];
        *(float4*)&dst[0] = make_float4(acc[i][0], acc[i][1], acc[i][2], acc[i][3]);
        *(float4*)&dst[4] = make_float4(acc[i][4], acc[i][5], acc[i][6], acc[i][7]);
    }
}

// ---------------------------------------------------------------------------
// Output projection: out[4096,64] = g_o[4096,768] @ Wo[768,64] + bo
// ---------------------------------------------------------------------------
__global__ __launch_bounds__(256) void oproj_kernel(
    const float* __restrict__ Wo, const float* __restrict__ bo,
    float* __restrict__ out)
{
    int row0 = blockIdx.x * 64;
    __shared__ float sA[16][64];
    __shared__ float sB[16][64];
    int tid = threadIdx.x, tx = tid & 15, ty = tid >> 4;

    float acc[4][4];
#pragma unroll
    for (int i = 0; i < 4; i++)
#pragma unroll
        for (int j = 0; j < 4; j++) acc[i][j] = 0.f;

    for (int k0 = 0; k0 < DINE; k0 += 16) {
        {
            int r = tid >> 2, kq = tid & 3;
            float4 a = *(const float4*)&g_o[(size_t)(row0 + r) * DINE + k0 + 4 * kq];
            sA[4*kq+0][r] = a.x; sA[4*kq+1][r] = a.y;
            sA[4*kq+2][r] = a.z; sA[4*kq+3][r] = a.w;
        }
        {
            int kk = tid >> 4, c4 = tid & 15;
            *(float4*)&sB[kk][4*c4] = *(const float4*)&Wo[(size_t)(k0+kk)*DD + 4*c4];
        }
        __syncthreads();
#pragma unroll
        for (int kk = 0; kk < 16; kk++) {
            float4 a = *(float4*)&sA[kk][ty*4];
            float4 b = *(float4*)&sB[kk][tx*4];
            float av[4] = {a.x,a.y,a.z,a.w};
            float bv[4] = {b.x,b.y,b.z,b.w};
#pragma unroll
            for (int i = 0; i < 4; i++)
#pragma unroll
                for (int j = 0; j < 4; j++)
                    acc[i][j] = fmaf(av[i], bv[j], acc[i][j]);
        }
        __syncthreads();
    }
    float4 bias = *(const float4*)&bo[tx*4];
    float bv[4] = {bias.x, bias.y, bias.z, bias.w};
#pragma unroll
    for (int i = 0; i < 4; i++) {
        int row = row0 + ty*4 + i;
        float4 v = make_float4(acc[i][0]+bv[0], acc[i][1]+bv[1],
                               acc[i][2]+bv[2], acc[i][3]+bv[3]);
        *(float4*)&out[(size_t)row * DD + tx*4] = v;
    }
}

// ---------------------------------------------------------------------------
extern "C" void kernel_launch(void* const* d_in, const int* in_sizes, int n_in,
                              void* d_out, int out_size)
{
    const float* x  = (const float*)d_in[0];
    const float* Wq = (const float*)d_in[1];
    const float* Wk = (const float*)d_in[2];
    const float* Wv = (const float*)d_in[3];
    const float* Wo = (const float*)d_in[4];
    const float* bo = (const float*)d_in[5];
    float* out = (float*)d_out;

    const long NTD = (long)NBB * TT * DD;            // 262144
    float* attn = out + NTD;                         // attn output doubles as S scratch

    int smem_s = 2 * 64 * QSTR * (int)sizeof(float); // 67584 B
    cudaFuncSetAttribute(sgemm_kernel, cudaFuncAttributeMaxDynamicSharedMemorySize, smem_s);

    qkv_kernel<<<dim3(32, 18), 256>>>(x, Wq, Wk, Wv);
    sgemm_kernel<<<dim3(36, NBH), 256, smem_s>>>(attn);
    softmax_kernel<<<dim3(128, NBH), 256>>>(attn);
    pv_kernel<<<dim3(8, NBH), 128>>>(attn);
    oproj_kernel<<<64, 256>>>(Wo, bo, out);
}

// round 8
// speedup vs baseline: 1.1079x; 1.1027x over previous
#include <cuda_runtime.h>
#include <cuda_bf16.h>
#include <mma.h>
#include <cstdint>
#include <math.h>

using namespace nvcuda;

#define HN   12
#define TT   1024
#define DD   64
#define DINE 768
#define NBB  4
#define NTR  (NBB*TT)   // 4096
#define NBH  (NBB*HN)   // 48

// Scratch (static device globals — allocation-free)
__device__ float g_q[NBB*HN*TT*DD];
__device__ float g_k[NBB*HN*TT*DD];
__device__ float g_v[NBB*HN*TT*DD];
__device__ float g_o[NTR*DINE];
__device__ __nv_bfloat16 g_x_hi[NTR*DINE];
__device__ __nv_bfloat16 g_x_lo[NTR*DINE];
__device__ __nv_bfloat16 g_w_hi[36*DINE*DD];   // [mh][k][n] (native layout)
__device__ __nv_bfloat16 g_w_lo[36*DINE*DD];

// Fast exp on the FMA pipe. x <= 0 expected.
__device__ __forceinline__ float fexp(float x) {
    x = fmaxf(x, -87.0f);
    float y = x * 1.44269504088896f;
    int   n = __float2int_rn(y);
    float f = y - (float)n;
    float p = 1.53989348e-4f;
    p = fmaf(p, f, 1.33336246e-3f);
    p = fmaf(p, f, 9.61812910e-3f);
    p = fmaf(p, f, 5.55041087e-2f);
    p = fmaf(p, f, 2.40226507e-1f);
    p = fmaf(p, f, 6.93147181e-1f);
    p = fmaf(p, f, 1.0f);
    return p * __int_as_float((n + 127) << 23);
}

// ---------------------------------------------------------------------------
// Convert X -> bf16 hi/lo (coalesced)
// ---------------------------------------------------------------------------
__global__ __launch_bounds__(256) void cvt_x_kernel(const float* __restrict__ x)
{
    int i = blockIdx.x * 256 + threadIdx.x;      // float4 index; 786432 total
    float4 v = ((const float4*)x)[i];
    __nv_bfloat162 h0 = __floats2bfloat162_rn(v.x, v.y);
    __nv_bfloat162 h1 = __floats2bfloat162_rn(v.z, v.w);
    float2 f0 = __bfloat1622float2(h0);
    float2 f1 = __bfloat1622float2(h1);
    __nv_bfloat162 l0 = __floats2bfloat162_rn(v.x - f0.x, v.y - f0.y);
    __nv_bfloat162 l1 = __floats2bfloat162_rn(v.z - f1.x, v.w - f1.y);
    ((__nv_bfloat162*)g_x_hi)[2*i]   = h0;
    ((__nv_bfloat162*)g_x_hi)[2*i+1] = h1;
    ((__nv_bfloat162*)g_x_lo)[2*i]   = l0;
    ((__nv_bfloat162*)g_x_lo)[2*i+1] = l1;
}

// ---------------------------------------------------------------------------
// Convert W -> bf16 hi/lo, native [h][k][n] layout (coalesced, no transpose)
// ---------------------------------------------------------------------------
__global__ __launch_bounds__(256) void cvt_w_kernel(
    const float* __restrict__ Wq, const float* __restrict__ Wk,
    const float* __restrict__ Wv)
{
    int mat = blockIdx.y;
    const float* Wm = (mat == 0 ? Wq : mat == 1 ? Wk : Wv);
    size_t base = (size_t)mat * HN * DINE * DD;   // bf16 elem offset / 4 floats
    int i = blockIdx.x * 256 + threadIdx.x;       // float4 index; 147456 per mat
    float4 v = ((const float4*)Wm)[i];
    __nv_bfloat162 h0 = __floats2bfloat162_rn(v.x, v.y);
    __nv_bfloat162 h1 = __floats2bfloat162_rn(v.z, v.w);
    float2 f0 = __bfloat1622float2(h0);
    float2 f1 = __bfloat1622float2(h1);
    __nv_bfloat162 l0 = __floats2bfloat162_rn(v.x - f0.x, v.y - f0.y);
    __nv_bfloat162 l1 = __floats2bfloat162_rn(v.z - f1.x, v.w - f1.y);
    ((__nv_bfloat162*)(g_w_hi + base))[2*i]   = h0;
    ((__nv_bfloat162*)(g_w_hi + base))[2*i+1] = h1;
    ((__nv_bfloat162*)(g_w_lo + base))[2*i]   = l0;
    ((__nv_bfloat162*)(g_w_lo + base))[2*i+1] = l1;
}

// ---------------------------------------------------------------------------
// QKV via WMMA bf16 hi/lo split: per CTA 128 rows x one (mat,head) 64 cols.
// 8 warps in 4x2; warp tile 32x32 = 2x2 wmma 16x16 frags; 3-term split MMA.
// ---------------------------------------------------------------------------
#define ASTR 24   // bf16 stride: rows bank-distinct for ldmatrix, mult of 8
#define BSTR 72

__global__ __launch_bounds__(256) void qkv_tc_kernel()
{
    __shared__ __align__(32) __nv_bfloat16 sAh[128*ASTR], sAl[128*ASTR];
    __shared__ __align__(32) __nv_bfloat16 sBh[16*BSTR],  sBl[16*BSTR];

    int rt = blockIdx.x;              // 0..31: 128-row tile
    int mh = blockIdx.y;              // 0..35
    int row0 = rt * 128;
    int tid = threadIdx.x, warp = tid >> 5;
    int wm = warp & 3, wn = warp >> 2;   // warp rows wm*32, cols wn*32

    const __nv_bfloat16* wh = g_w_hi + (size_t)mh * DINE * DD;
    const __nv_bfloat16* wl = g_w_lo + (size_t)mh * DINE * DD;

    wmma::fragment<wmma::accumulator, 16, 16, 16, float> c[2][2];
#pragma unroll
    for (int mi = 0; mi < 2; mi++)
#pragma unroll
        for (int ni = 0; ni < 2; ni++) wmma::fill_fragment(c[mi][ni], 0.0f);

    for (int k0 = 0; k0 < DINE; k0 += 16) {
        // A: 128x16 hi+lo. 256 threads x one uint4 (8 bf16) each.
        {
            int r = tid >> 1, hf = tid & 1;
            size_t src = (size_t)(row0 + r) * DINE + k0 + hf * 8;
            *(uint4*)&sAh[r*ASTR + hf*8] = *(const uint4*)&g_x_hi[src];
            *(uint4*)&sAl[r*ASTR + hf*8] = *(const uint4*)&g_x_lo[src];
        }
        // B: 16x64 hi+lo. first 128 threads x one uint4 each.
        if (tid < 128) {
            int r = tid >> 3, cc = (tid & 7) * 8;
            size_t src = (size_t)(k0 + r) * DD + cc;
            *(uint4*)&sBh[r*BSTR + cc] = *(const uint4*)&wh[src];
            *(uint4*)&sBl[r*BSTR + cc] = *(const uint4*)&wl[src];
        }
        __syncthreads();

        wmma::fragment<wmma::matrix_a, 16, 16, 16, __nv_bfloat16, wmma::row_major> ah[2], al[2];
        wmma::fragment<wmma::matrix_b, 16, 16, 16, __nv_bfloat16, wmma::row_major> bh[2], bl[2];
#pragma unroll
        for (int mi = 0; mi < 2; mi++) {
            wmma::load_matrix_sync(ah[mi], &sAh[(wm*32 + mi*16) * ASTR], ASTR);
            wmma::load_matrix_sync(al[mi], &sAl[(wm*32 + mi*16) * ASTR], ASTR);
        }
#pragma unroll
        for (int ni = 0; ni < 2; ni++) {
            wmma::load_matrix_sync(bh[ni], &sBh[wn*32 + ni*16], BSTR);
            wmma::load_matrix_sync(bl[ni], &sBl[wn*32 + ni*16], BSTR);
        }
#pragma unroll
        for (int mi = 0; mi < 2; mi++)
#pragma unroll
            for (int ni = 0; ni < 2; ni++) {
                wmma::mma_sync(c[mi][ni], ah[mi], bh[ni], c[mi][ni]);
                wmma::mma_sync(c[mi][ni], ah[mi], bl[ni], c[mi][ni]);
                wmma::mma_sync(c[mi][ni], al[mi], bh[ni], c[mi][ni]);
            }
        __syncthreads();
    }

    int mat = mh / HN, h = mh % HN;
    float* outp = (mat == 0 ? g_q : mat == 1 ? g_k : g_v);
    int rowb = row0 + wm*32;
    int n = rowb >> 10, t0 = rowb & (TT - 1);     // 128-tile stays in one n
    float* dst = outp + ((size_t)(n*HN + h)*TT + t0) * DD + wn*32;
#pragma unroll
    for (int mi = 0; mi < 2; mi++)
#pragma unroll
        for (int ni = 0; ni < 2; ni++)
            wmma::store_matrix_sync(dst + (size_t)mi*16*DD + ni*16, c[mi][ni],
                                    DD, wmma::mem_row_major);
}

// ---------------------------------------------------------------------------
// S = Q @ K^T, per (bh, lower-triangle 128x128 block). Raw scores -> attn buf.
// ---------------------------------------------------------------------------
#define QSTR 132
__global__ __launch_bounds__(256) void sgemm_kernel(float* __restrict__ attn)
{
    extern __shared__ float sm[];
    float* sQt = sm;
    float* sKt = sm + 64 * QSTR;

    int idx = blockIdx.x, rb = 0;
    while (idx > rb) { idx -= rb + 1; rb++; }
    int cb = idx;
    int bh = blockIdx.y;

    const float* qp = g_q + (size_t)bh * TT * DD + (size_t)rb * 128 * DD;
    const float* kp = g_k + (size_t)bh * TT * DD + (size_t)cb * 128 * DD;

    int tid = threadIdx.x;
    int tx = tid & 15, ty = tid >> 4;

#pragma unroll
    for (int i = 0; i < 8; i++) {
        int v = tid + 256 * i;
        int r = v >> 4, e4 = v & 15;
        float4 q = *(const float4*)&qp[(size_t)r * DD + 4 * e4];
        sQt[(4*e4+0)*QSTR + r] = q.x; sQt[(4*e4+1)*QSTR + r] = q.y;
        sQt[(4*e4+2)*QSTR + r] = q.z; sQt[(4*e4+3)*QSTR + r] = q.w;
        float4 k = *(const float4*)&kp[(size_t)r * DD + 4 * e4];
        sKt[(4*e4+0)*QSTR + r] = k.x; sKt[(4*e4+1)*QSTR + r] = k.y;
        sKt[(4*e4+2)*QSTR + r] = k.z; sKt[(4*e4+3)*QSTR + r] = k.w;
    }
    __syncthreads();

    float acc[8][8];
#pragma unroll
    for (int i = 0; i < 8; i++)
#pragma unroll
        for (int j = 0; j < 8; j++) acc[i][j] = 0.f;

#pragma unroll 4
    for (int e = 0; e < 64; e++) {
        float4 a0 = *(float4*)&sQt[e*QSTR + ty*8];
        float4 a1 = *(float4*)&sQt[e*QSTR + ty*8 + 4];
        float4 b0 = *(float4*)&sKt[e*QSTR + tx*8];
        float4 b1 = *(float4*)&sKt[e*QSTR + tx*8 + 4];
        float av[8] = {a0.x,a0.y,a0.z,a0.w,a1.x,a1.y,a1.z,a1.w};
        float bv[8] = {b0.x,b0.y,b0.z,b0.w,b1.x,b1.y,b1.z,b1.w};
#pragma unroll
        for (int i = 0; i < 8; i++)
#pragma unroll
            for (int j = 0; j < 8; j++)
                acc[i][j] = fmaf(av[i], bv[j], acc[i][j]);
    }

#pragma unroll
    for (int i = 0; i < 8; i++) {
        int row = rb*128 + ty*8 + i;
        float* dst = &attn[((size_t)bh * TT + row) * TT + cb*128 + tx*8];
        *(float4*)&dst[0] = make_float4(acc[i][0], acc[i][1], acc[i][2], acc[i][3]);
        *(float4*)&dst[4] = make_float4(acc[i][4], acc[i][5], acc[i][6], acc[i][7]);
    }
}

// ---------------------------------------------------------------------------
// Softmax (causal + "==0 -> -inf" quirk), one warp per row.
// ---------------------------------------------------------------------------
__global__ __launch_bounds__(256) void softmax_kernel(float* __restrict__ attn)
{
    int tid = threadIdx.x, lane = tid & 31, warp = tid >> 5;
    int tq = blockIdx.x * 8 + warp;
    int bh = blockIdx.y;
    float* row = attn + ((size_t)bh * TT + tq) * TT;
    int len = tq + 1;

    float pv[32];
    float mx = -INFINITY;
#pragma unroll
    for (int k = 0; k < 32; k++) {
        int s = lane + 32 * k;
        if (s < len) {
            float v = row[s];
            pv[k] = (v == 0.0f) ? -INFINITY : v;
            mx = fmaxf(mx, pv[k]);
        } else pv[k] = -INFINITY;
    }
#pragma unroll
    for (int o = 16; o > 0; o >>= 1) mx = fmaxf(mx, __shfl_xor_sync(0xffffffffu, mx, o));

    float sum = 0.f;
#pragma unroll
    for (int k = 0; k < 32; k++) {
        int s = lane + 32 * k;
        if (s < len) { pv[k] = fexp(pv[k] - mx); sum += pv[k]; }
        else pv[k] = 0.f;
    }
#pragma unroll
    for (int o = 16; o > 0; o >>= 1) sum += __shfl_xor_sync(0xffffffffu, sum, o);
    float inv = 1.f / sum;

#pragma unroll
    for (int k = 0; k < 32; k++) {
        int s = lane + 32 * k;
        row[s] = pv[k] * inv;
    }
}

// ---------------------------------------------------------------------------
// O = P @ V, per (bh, 64-row block). 128 threads, 4x8 microtile.
// ---------------------------------------------------------------------------
#define PSTR 68
#define VSTR 68
__global__ __launch_bounds__(128) void pv_kernel(const float* __restrict__ attn)
{
    __shared__ float sPt[32 * PSTR];   // [s][row]  (64 rows)
    __shared__ float sV [32 * VSTR];   // [s][d]

    int rt = 15 - blockIdx.x;          // heavy tiles first
    int bh = blockIdx.y;
    int row0 = rt * 64;
    int kmax = (rt + 1) * 64;
    const float* vp = g_v + (size_t)bh * TT * DD;
    const float* pp = attn + ((size_t)bh * TT + row0) * TT;

    int tid = threadIdx.x;
    int tx = tid & 7, ty = tid >> 3;

    float acc[4][8];
#pragma unroll
    for (int i = 0; i < 4; i++)
#pragma unroll
        for (int j = 0; j < 8; j++) acc[i][j] = 0.f;

    for (int sb = 0; sb < kmax; sb += 32) {
#pragma unroll
        for (int i = 0; i < 4; i++) {              // P chunk 64x32, transposed
            int v = tid + 128 * i;
            int r = v >> 3, e4 = v & 7;
            float4 p = *(const float4*)&pp[(size_t)r * TT + sb + 4 * e4];
            sPt[(4*e4+0)*PSTR + r] = p.x; sPt[(4*e4+1)*PSTR + r] = p.y;
            sPt[(4*e4+2)*PSTR + r] = p.z; sPt[(4*e4+3)*PSTR + r] = p.w;
        }
#pragma unroll
        for (int i = 0; i < 4; i++) {              // V chunk 32x64
            int v = tid + 128 * i;
            int s = v >> 4, c4 = v & 15;
            *(float4*)&sV[s * VSTR + 4 * c4] =
                *(const float4*)&vp[(size_t)(sb + s) * DD + 4 * c4];
        }
        __syncthreads();
#pragma unroll 4
        for (int s = 0; s < 32; s++) {
            float4 a  = *(float4*)&sPt[s*PSTR + ty*4];
            float4 b0 = *(float4*)&sV[s*VSTR + tx*8];
            float4 b1 = *(float4*)&sV[s*VSTR + tx*8 + 4];
            float av[4] = {a.x,a.y,a.z,a.w};
            float bv[8] = {b0.x,b0.y,b0.z,b0.w,b1.x,b1.y,b1.z,b1.w};
#pragma unroll
            for (int i = 0; i < 4; i++)
#pragma unroll
                for (int j = 0; j < 8; j++)
                    acc[i][j] = fmaf(av[i], bv[j], acc[i][j]);
        }
        __syncthreads();
    }

    int n = bh / HN, h = bh % HN;
#pragma unroll
    for (int i = 0; i < 4; i++) {
        int t = row0 + ty*4 + i;
        float* dst = &g_o[(size_t)(n*TT + t) * DINE + h*DD + tx*8];
        *(float4*)&dst[0] = make_float4(acc[i][0], acc[i][1], acc[i][2], acc[i][3]);
        *(float4*)&dst[4] = make_float4(acc[i][4], acc[i][5], acc[i][6], acc[i][7]);
    }
}

// ---------------------------------------------------------------------------
// Output projection: out[4096,64] = g_o[4096,768] @ Wo[768,64] + bo
// ---------------------------------------------------------------------------
__global__ __launch_bounds__(256) void oproj_kernel(
    const float* __restrict__ Wo, const float* __restrict__ bo,
    float* __restrict__ out)
{
    int row0 = blockIdx.x * 64;
    __shared__ float sA[16][64];
    __shared__ float sB[16][64];
    int tid = threadIdx.x, tx = tid & 15, ty = tid >> 4;

    float acc[4][4];
#pragma unroll
    for (int i = 0; i < 4; i++)
#pragma unroll
        for (int j = 0; j < 4; j++) acc[i][j] = 0.f;

    for (int k0 = 0; k0 < DINE; k0 += 16) {
        {
            int r = tid >> 2, kq = tid & 3;
            float4 a = *(const float4*)&g_o[(size_t)(row0 + r) * DINE + k0 + 4 * kq];
            sA[4*kq+0][r] = a.x; sA[4*kq+1][r] = a.y;
            sA[4*kq+2][r] = a.z; sA[4*kq+3][r] = a.w;
        }
        {
            int kk = tid >> 4, c4 = tid & 15;
            *(float4*)&sB[kk][4*c4] = *(const float4*)&Wo[(size_t)(k0+kk)*DD + 4*c4];
        }
        __syncthreads();
#pragma unroll
        for (int kk = 0; kk < 16; kk++) {
            float4 a = *(float4*)&sA[kk][ty*4];
            float4 b = *(float4*)&sB[kk][tx*4];
            float av[4] = {a.x,a.y,a.z,a.w};
            float bv[4] = {b.x,b.y,b.z,b.w};
#pragma unroll
            for (int i = 0; i < 4; i++)
#pragma unroll
                for (int j = 0; j < 4; j++)
                    acc[i][j] = fmaf(av[i], bv[j], acc[i][j]);
        }
        __syncthreads();
    }
    float4 bias = *(const float4*)&bo[tx*4];
    float bv[4] = {bias.x, bias.y, bias.z, bias.w};
#pragma unroll
    for (int i = 0; i < 4; i++) {
        int row = row0 + ty*4 + i;
        float4 v = make_float4(acc[i][0]+bv[0], acc[i][1]+bv[1],
                               acc[i][2]+bv[2], acc[i][3]+bv[3]);
        *(float4*)&out[(size_t)row * DD + tx*4] = v;
    }
}

// ---------------------------------------------------------------------------
extern "C" void kernel_launch(void* const* d_in, const int* in_sizes, int n_in,
                              void* d_out, int out_size)
{
    const float* x  = (const float*)d_in[0];
    const float* Wq = (const float*)d_in[1];
    const float* Wk = (const float*)d_in[2];
    const float* Wv = (const float*)d_in[3];
    const float* Wo = (const float*)d_in[4];
    const float* bo = (const float*)d_in[5];
    float* out = (float*)d_out;

    const long NTD = (long)NBB * TT * DD;
    float* attn = out + NTD;

    int smem_s = 2 * 64 * QSTR * (int)sizeof(float);  // 67584
    cudaFuncSetAttribute(sgemm_kernel, cudaFuncAttributeMaxDynamicSharedMemorySize, smem_s);

    cvt_x_kernel<<<NTR*DINE/1024, 256>>>(x);
    cvt_w_kernel<<<dim3(576, 3), 256>>>(Wq, Wk, Wv);
    qkv_tc_kernel<<<dim3(32, 36), 256>>>();
    sgemm_kernel<<<dim3(36, NBH), 256, smem_s>>>(attn);
    softmax_kernel<<<dim3(128, NBH), 256>>>(attn);
    pv_kernel<<<dim3(16, NBH), 128>>>(attn);
    oproj_kernel<<<64, 256>>>(Wo, bo, out);
}

// round 9
// speedup vs baseline: 1.6038x; 1.4476x over previous
#include <cuda_runtime.h>
#include <cuda_bf16.h>
#include <mma.h>
#include <cstdint>
#include <math.h>

using namespace nvcuda;

#define HN   12
#define TT   1024
#define DD   64
#define DINE 768
#define NBB  4
#define NTR  (NBB*TT)   // 4096
#define NBH  (NBB*HN)   // 48

// Scratch (static device globals — allocation-free)
__device__ float g_q[NBB*HN*TT*DD];
__device__ float g_k[NBB*HN*TT*DD];
__device__ float g_v[NBB*HN*TT*DD];
__device__ float g_o[NTR*DINE];
__device__ __nv_bfloat16 g_x_hi[NTR*DINE];
__device__ __nv_bfloat16 g_x_lo[NTR*DINE];
__device__ __nv_bfloat16 g_w_hi[36*DINE*DD];   // [mh][k][n]
__device__ __nv_bfloat16 g_w_lo[36*DINE*DD];
__device__ __nv_bfloat16 g_qh[NBH*TT*DD], g_ql[NBH*TT*DD];
__device__ __nv_bfloat16 g_kh[NBH*TT*DD], g_kl[NBH*TT*DD];
__device__ __nv_bfloat16 g_vh[NBH*TT*DD], g_vl[NBH*TT*DD];

// Fast exp on the FMA pipe. x <= 0 expected (handles -inf via clamp).
__device__ __forceinline__ float fexp(float x) {
    x = fmaxf(x, -87.0f);
    float y = x * 1.44269504088896f;
    int   n = __float2int_rn(y);
    float f = y - (float)n;
    float p = 1.53989348e-4f;
    p = fmaf(p, f, 1.33336246e-3f);
    p = fmaf(p, f, 9.61812910e-3f);
    p = fmaf(p, f, 5.55041087e-2f);
    p = fmaf(p, f, 2.40226507e-1f);
    p = fmaf(p, f, 6.93147181e-1f);
    p = fmaf(p, f, 1.0f);
    return p * __int_as_float((n + 127) << 23);
}

// ---------------------------------------------------------------------------
// Convert X -> bf16 hi/lo
// ---------------------------------------------------------------------------
__global__ __launch_bounds__(256) void cvt_x_kernel(const float* __restrict__ x)
{
    int i = blockIdx.x * 256 + threadIdx.x;      // float4 index
    float4 v = ((const float4*)x)[i];
    __nv_bfloat162 h0 = __floats2bfloat162_rn(v.x, v.y);
    __nv_bfloat162 h1 = __floats2bfloat162_rn(v.z, v.w);
    float2 f0 = __bfloat1622float2(h0);
    float2 f1 = __bfloat1622float2(h1);
    __nv_bfloat162 l0 = __floats2bfloat162_rn(v.x - f0.x, v.y - f0.y);
    __nv_bfloat162 l1 = __floats2bfloat162_rn(v.z - f1.x, v.w - f1.y);
    ((__nv_bfloat162*)g_x_hi)[2*i]   = h0;
    ((__nv_bfloat162*)g_x_hi)[2*i+1] = h1;
    ((__nv_bfloat162*)g_x_lo)[2*i]   = l0;
    ((__nv_bfloat162*)g_x_lo)[2*i+1] = l1;
}

// ---------------------------------------------------------------------------
// Convert W -> bf16 hi/lo, native [h][k][n]
// ---------------------------------------------------------------------------
__global__ __launch_bounds__(256) void cvt_w_kernel(
    const float* __restrict__ Wq, const float* __restrict__ Wk,
    const float* __restrict__ Wv)
{
    int mat = blockIdx.y;
    const float* Wm = (mat == 0 ? Wq : mat == 1 ? Wk : Wv);
    size_t base = (size_t)mat * HN * DINE * DD;
    int i = blockIdx.x * 256 + threadIdx.x;
    float4 v = ((const float4*)Wm)[i];
    __nv_bfloat162 h0 = __floats2bfloat162_rn(v.x, v.y);
    __nv_bfloat162 h1 = __floats2bfloat162_rn(v.z, v.w);
    float2 f0 = __bfloat1622float2(h0);
    float2 f1 = __bfloat1622float2(h1);
    __nv_bfloat162 l0 = __floats2bfloat162_rn(v.x - f0.x, v.y - f0.y);
    __nv_bfloat162 l1 = __floats2bfloat162_rn(v.z - f1.x, v.w - f1.y);
    ((__nv_bfloat162*)(g_w_hi + base))[2*i]   = h0;
    ((__nv_bfloat162*)(g_w_hi + base))[2*i+1] = h1;
    ((__nv_bfloat162*)(g_w_lo + base))[2*i]   = l0;
    ((__nv_bfloat162*)(g_w_lo + base))[2*i+1] = l1;
}

// ---------------------------------------------------------------------------
// Convert Q/K/V fp32 -> bf16 hi/lo
// ---------------------------------------------------------------------------
__global__ __launch_bounds__(256) void cvt_qkv_kernel()
{
    int mat = blockIdx.y;
    const float* src = (mat == 0 ? g_q : mat == 1 ? g_k : g_v);
    __nv_bfloat16* dh = (mat == 0 ? g_qh : mat == 1 ? g_kh : g_vh);
    __nv_bfloat16* dl = (mat == 0 ? g_ql : mat == 1 ? g_kl : g_vl);
    int i = blockIdx.x * 256 + threadIdx.x;
    float4 v = ((const float4*)src)[i];
    __nv_bfloat162 h0 = __floats2bfloat162_rn(v.x, v.y);
    __nv_bfloat162 h1 = __floats2bfloat162_rn(v.z, v.w);
    float2 f0 = __bfloat1622float2(h0);
    float2 f1 = __bfloat1622float2(h1);
    __nv_bfloat162 l0 = __floats2bfloat162_rn(v.x - f0.x, v.y - f0.y);
    __nv_bfloat162 l1 = __floats2bfloat162_rn(v.z - f1.x, v.w - f1.y);
    ((__nv_bfloat162*)dh)[2*i]   = h0;
    ((__nv_bfloat162*)dh)[2*i+1] = h1;
    ((__nv_bfloat162*)dl)[2*i]   = l0;
    ((__nv_bfloat162*)dl)[2*i+1] = l1;
}

// ---------------------------------------------------------------------------
// QKV via WMMA bf16 hi/lo split (unchanged from R8)
// ---------------------------------------------------------------------------
#define ASTR 24
#define BSTR 72

__global__ __launch_bounds__(256) void qkv_tc_kernel()
{
    __shared__ __align__(32) __nv_bfloat16 sAh[128*ASTR], sAl[128*ASTR];
    __shared__ __align__(32) __nv_bfloat16 sBh[16*BSTR],  sBl[16*BSTR];

    int rt = blockIdx.x, mh = blockIdx.y;
    int row0 = rt * 128;
    int tid = threadIdx.x, warp = tid >> 5;
    int wm = warp & 3, wn = warp >> 2;

    const __nv_bfloat16* wh = g_w_hi + (size_t)mh * DINE * DD;
    const __nv_bfloat16* wl = g_w_lo + (size_t)mh * DINE * DD;

    wmma::fragment<wmma::accumulator, 16, 16, 16, float> c[2][2];
#pragma unroll
    for (int mi = 0; mi < 2; mi++)
#pragma unroll
        for (int ni = 0; ni < 2; ni++) wmma::fill_fragment(c[mi][ni], 0.0f);

    for (int k0 = 0; k0 < DINE; k0 += 16) {
        {
            int r = tid >> 1, hf = tid & 1;
            size_t src = (size_t)(row0 + r) * DINE + k0 + hf * 8;
            *(uint4*)&sAh[r*ASTR + hf*8] = *(const uint4*)&g_x_hi[src];
            *(uint4*)&sAl[r*ASTR + hf*8] = *(const uint4*)&g_x_lo[src];
        }
        if (tid < 128) {
            int r = tid >> 3, cc = (tid & 7) * 8;
            size_t src = (size_t)(k0 + r) * DD + cc;
            *(uint4*)&sBh[r*BSTR + cc] = *(const uint4*)&wh[src];
            *(uint4*)&sBl[r*BSTR + cc] = *(const uint4*)&wl[src];
        }
        __syncthreads();

        wmma::fragment<wmma::matrix_a, 16, 16, 16, __nv_bfloat16, wmma::row_major> ah[2], al[2];
        wmma::fragment<wmma::matrix_b, 16, 16, 16, __nv_bfloat16, wmma::row_major> bh[2], bl[2];
#pragma unroll
        for (int mi = 0; mi < 2; mi++) {
            wmma::load_matrix_sync(ah[mi], &sAh[(wm*32 + mi*16) * ASTR], ASTR);
            wmma::load_matrix_sync(al[mi], &sAl[(wm*32 + mi*16) * ASTR], ASTR);
        }
#pragma unroll
        for (int ni = 0; ni < 2; ni++) {
            wmma::load_matrix_sync(bh[ni], &sBh[wn*32 + ni*16], BSTR);
            wmma::load_matrix_sync(bl[ni], &sBl[wn*32 + ni*16], BSTR);
        }
#pragma unroll
        for (int mi = 0; mi < 2; mi++)
#pragma unroll
            for (int ni = 0; ni < 2; ni++) {
                wmma::mma_sync(c[mi][ni], ah[mi], bh[ni], c[mi][ni]);
                wmma::mma_sync(c[mi][ni], ah[mi], bl[ni], c[mi][ni]);
                wmma::mma_sync(c[mi][ni], al[mi], bh[ni], c[mi][ni]);
            }
        __syncthreads();
    }

    int mat = mh / HN, h = mh % HN;
    float* outp = (mat == 0 ? g_q : mat == 1 ? g_k : g_v);
    int rowb = row0 + wm*32;
    int n = rowb >> 10, t0 = rowb & (TT - 1);
    float* dst = outp + ((size_t)(n*HN + h)*TT + t0) * DD + wn*32;
#pragma unroll
    for (int mi = 0; mi < 2; mi++)
#pragma unroll
        for (int ni = 0; ni < 2; ni++)
            wmma::store_matrix_sync(dst + (size_t)mi*16*DD + ni*16, c[mi][ni],
                                    DD, wmma::mem_row_major);
}

// ---------------------------------------------------------------------------
// S = Q @ K^T via WMMA bf16 split, per (bh, lower-tri 128x128 block).
// K=64 in one shot. B fragments col_major directly over K rows.
// ---------------------------------------------------------------------------
#define QS 72
__global__ __launch_bounds__(256) void sgemm_tc_kernel(float* __restrict__ attn)
{
    extern __shared__ __nv_bfloat16 smb[];
    __nv_bfloat16* sQh = smb;
    __nv_bfloat16* sQl = smb + 128*QS;
    __nv_bfloat16* sKh = smb + 2*128*QS;
    __nv_bfloat16* sKl = smb + 3*128*QS;

    int idx = blockIdx.x, rb = 0;
    while (idx > rb) { idx -= rb + 1; rb++; }
    int cb = idx;
    int bh = blockIdx.y;

    const __nv_bfloat16* qh = g_qh + ((size_t)bh * TT + rb*128) * DD;
    const __nv_bfloat16* ql = g_ql + ((size_t)bh * TT + rb*128) * DD;
    const __nv_bfloat16* kh = g_kh + ((size_t)bh * TT + cb*128) * DD;
    const __nv_bfloat16* kl = g_kl + ((size_t)bh * TT + cb*128) * DD;

    int tid = threadIdx.x, warp = tid >> 5;
    int wm = warp & 3, wn = warp >> 2;   // warp tile: rows wm*32, cols wn*64

#pragma unroll
    for (int it = 0; it < 4; it++) {
        int v = tid + 256 * it;
        int r = v >> 3, cc = (v & 7) * 8;
        *(uint4*)&sQh[r*QS + cc] = *(const uint4*)&qh[(size_t)r*DD + cc];
        *(uint4*)&sQl[r*QS + cc] = *(const uint4*)&ql[(size_t)r*DD + cc];
        *(uint4*)&sKh[r*QS + cc] = *(const uint4*)&kh[(size_t)r*DD + cc];
        *(uint4*)&sKl[r*QS + cc] = *(const uint4*)&kl[(size_t)r*DD + cc];
    }
    __syncthreads();

    wmma::fragment<wmma::accumulator, 16, 16, 16, float> c[2][4];
#pragma unroll
    for (int mi = 0; mi < 2; mi++)
#pragma unroll
        for (int ni = 0; ni < 4; ni++) wmma::fill_fragment(c[mi][ni], 0.0f);

#pragma unroll
    for (int k0 = 0; k0 < 64; k0 += 16) {
        wmma::fragment<wmma::matrix_a, 16, 16, 16, __nv_bfloat16, wmma::row_major> ah[2], al[2];
#pragma unroll
        for (int mi = 0; mi < 2; mi++) {
            wmma::load_matrix_sync(ah[mi], &sQh[(wm*32 + mi*16)*QS + k0], QS);
            wmma::load_matrix_sync(al[mi], &sQl[(wm*32 + mi*16)*QS + k0], QS);
        }
#pragma unroll
        for (int ni = 0; ni < 4; ni++) {
            wmma::fragment<wmma::matrix_b, 16, 16, 16, __nv_bfloat16, wmma::col_major> bh, bl;
            wmma::load_matrix_sync(bh, &sKh[(wn*64 + ni*16)*QS + k0], QS);
            wmma::load_matrix_sync(bl, &sKl[(wn*64 + ni*16)*QS + k0], QS);
#pragma unroll
            for (int mi = 0; mi < 2; mi++) {
                wmma::mma_sync(c[mi][ni], ah[mi], bh, c[mi][ni]);
                wmma::mma_sync(c[mi][ni], ah[mi], bl, c[mi][ni]);
                wmma::mma_sync(c[mi][ni], al[mi], bh, c[mi][ni]);
            }
        }
    }

#pragma unroll
    for (int mi = 0; mi < 2; mi++)
#pragma unroll
        for (int ni = 0; ni < 4; ni++) {
            int row = rb*128 + wm*32 + mi*16;
            int col = cb*128 + wn*64 + ni*16;
            wmma::store_matrix_sync(&attn[((size_t)bh*TT + row)*TT + col],
                                    c[mi][ni], TT, wmma::mem_row_major);
        }
}

// ---------------------------------------------------------------------------
// Softmax (causal + "==0 -> -inf" quirk), one warp/row, float4 vectorized.
// ---------------------------------------------------------------------------
__global__ __launch_bounds__(256) void softmax_kernel(float* __restrict__ attn)
{
    int tid = threadIdx.x, lane = tid & 31, warp = tid >> 5;
    int tq = blockIdx.x * 8 + warp;
    int bh = blockIdx.y;
    float* row = attn + ((size_t)bh * TT + tq) * TT;
    int len = tq + 1;

    float4 pv4[8];
    float mx = -INFINITY;
#pragma unroll
    for (int j = 0; j < 8; j++) {
        int base = (j*32 + lane) * 4;
        float4 v = *(const float4*)&row[base];
        float* e = &v.x;
#pragma unroll
        for (int cq = 0; cq < 4; cq++) {
            float val = (base + cq < len) ? (e[cq] == 0.0f ? -INFINITY : e[cq])
                                          : -INFINITY;
            e[cq] = val;
            mx = fmaxf(mx, val);
        }
        pv4[j] = v;
    }
#pragma unroll
    for (int o = 16; o > 0; o >>= 1) mx = fmaxf(mx, __shfl_xor_sync(0xffffffffu, mx, o));

    float sum = 0.f;
#pragma unroll
    for (int j = 0; j < 8; j++) {
        int base = (j*32 + lane) * 4;
        float* e = &pv4[j].x;
#pragma unroll
        for (int cq = 0; cq < 4; cq++) {
            float p = (base + cq < len) ? fexp(e[cq] - mx) : 0.0f;
            e[cq] = p;
            sum += p;
        }
    }
#pragma unroll
    for (int o = 16; o > 0; o >>= 1) sum += __shfl_xor_sync(0xffffffffu, sum, o);
    float inv = 1.f / sum;

#pragma unroll
    for (int j = 0; j < 8; j++) {
        float4 v = pv4[j];
        v.x *= inv; v.y *= inv; v.z *= inv; v.w *= inv;
        *(float4*)&row[(j*32 + lane) * 4] = v;
    }
}

// ---------------------------------------------------------------------------
// O = P @ V via WMMA: P converted fp32->bf16 hi/lo in-kernel; V bf16 hi/lo.
// Per (bh, 128-row tile); chunks of 32 keys.
// ---------------------------------------------------------------------------
#define PS 40
#define VS 72
__global__ __launch_bounds__(256) void pv_tc_kernel(const float* __restrict__ attn)
{
    __shared__ __align__(32) __nv_bfloat16 sPh[128*PS], sPl[128*PS];
    __shared__ __align__(32) __nv_bfloat16 sVh[32*VS],  sVl[32*VS];

    int rb = 7 - blockIdx.x;           // heavy tiles first
    int bh = blockIdx.y;
    int row0 = rb * 128;
    int kmax = (rb + 1) * 128;
    const float* pp = attn + ((size_t)bh * TT + row0) * TT;
    const __nv_bfloat16* vh = g_vh + (size_t)bh * TT * DD;
    const __nv_bfloat16* vl = g_vl + (size_t)bh * TT * DD;

    int tid = threadIdx.x, warp = tid >> 5;
    int wm = warp & 3, wn = warp >> 2;   // warp tile: rows wm*32, cols wn*32

    wmma::fragment<wmma::accumulator, 16, 16, 16, float> c[2][2];
#pragma unroll
    for (int mi = 0; mi < 2; mi++)
#pragma unroll
        for (int ni = 0; ni < 2; ni++) wmma::fill_fragment(c[mi][ni], 0.0f);

    for (int sb = 0; sb < kmax; sb += 32) {
        // P chunk 128x32 fp32 -> bf16 hi/lo smem
#pragma unroll
        for (int it = 0; it < 4; it++) {
            int v = tid + 256 * it;
            int r = v >> 3, c4 = (v & 7) * 4;
            float4 p = *(const float4*)&pp[(size_t)r * TT + sb + c4];
            __nv_bfloat162 h0 = __floats2bfloat162_rn(p.x, p.y);
            __nv_bfloat162 h1 = __floats2bfloat162_rn(p.z, p.w);
            float2 f0 = __bfloat1622float2(h0);
            float2 f1 = __bfloat1622float2(h1);
            __nv_bfloat162 l0 = __floats2bfloat162_rn(p.x - f0.x, p.y - f0.y);
            __nv_bfloat162 l1 = __floats2bfloat162_rn(p.z - f1.x, p.w - f1.y);
            *(__nv_bfloat162*)&sPh[r*PS + c4]     = h0;
            *(__nv_bfloat162*)&sPh[r*PS + c4 + 2] = h1;
            *(__nv_bfloat162*)&sPl[r*PS + c4]     = l0;
            *(__nv_bfloat162*)&sPl[r*PS + c4 + 2] = l1;
        }
        // V chunk 32x64 bf16 hi/lo
        {
            int r = tid >> 3, cc = (tid & 7) * 8;
            *(uint4*)&sVh[r*VS + cc] = *(const uint4*)&vh[(size_t)(sb + r)*DD + cc];
            *(uint4*)&sVl[r*VS + cc] = *(const uint4*)&vl[(size_t)(sb + r)*DD + cc];
        }
        __syncthreads();

#pragma unroll
        for (int k0 = 0; k0 < 32; k0 += 16) {
            wmma::fragment<wmma::matrix_a, 16, 16, 16, __nv_bfloat16, wmma::row_major> ah[2], al[2];
#pragma unroll
            for (int mi = 0; mi < 2; mi++) {
                wmma::load_matrix_sync(ah[mi], &sPh[(wm*32 + mi*16)*PS + k0], PS);
                wmma::load_matrix_sync(al[mi], &sPl[(wm*32 + mi*16)*PS + k0], PS);
            }
#pragma unroll
            for (int ni = 0; ni < 2; ni++) {
                wmma::fragment<wmma::matrix_b, 16, 16, 16, __nv_bfloat16, wmma::row_major> bh, bl;
                wmma::load_matrix_sync(bh, &sVh[k0*VS + wn*32 + ni*16], VS);
                wmma::load_matrix_sync(bl, &sVl[k0*VS + wn*32 + ni*16], VS);
#pragma unroll
                for (int mi = 0; mi < 2; mi++) {
                    wmma::mma_sync(c[mi][ni], ah[mi], bh, c[mi][ni]);
                    wmma::mma_sync(c[mi][ni], ah[mi], bl, c[mi][ni]);
                    wmma::mma_sync(c[mi][ni], al[mi], bh, c[mi][ni]);
                }
            }
        }
        __syncthreads();
    }

    int n = bh / HN, h = bh % HN;
#pragma unroll
    for (int mi = 0; mi < 2; mi++)
#pragma unroll
        for (int ni = 0; ni < 2; ni++) {
            int t = row0 + wm*32 + mi*16;
            wmma::store_matrix_sync(
                &g_o[((size_t)(n*TT + t))*DINE + h*DD + wn*32 + ni*16],
                c[mi][ni], DINE, wmma::mem_row_major);
        }
}

// ---------------------------------------------------------------------------
// Output projection: out[4096,64] = g_o[4096,768] @ Wo[768,64] + bo
// ---------------------------------------------------------------------------
__global__ __launch_bounds__(256) void oproj_kernel(
    const float* __restrict__ Wo, const float* __restrict__ bo,
    float* __restrict__ out)
{
    int row0 = blockIdx.x * 64;
    __shared__ float sA[16][64];
    __shared__ float sB[16][64];
    int tid = threadIdx.x, tx = tid & 15, ty = tid >> 4;

    float acc[4][4];
#pragma unroll
    for (int i = 0; i < 4; i++)
#pragma unroll
        for (int j = 0; j < 4; j++) acc[i][j] = 0.f;

    for (int k0 = 0; k0 < DINE; k0 += 16) {
        {
            int r = tid >> 2, kq = tid & 3;
            float4 a = *(const float4*)&g_o[(size_t)(row0 + r) * DINE + k0 + 4 * kq];
            sA[4*kq+0][r] = a.x; sA[4*kq+1][r] = a.y;
            sA[4*kq+2][r] = a.z; sA[4*kq+3][r] = a.w;
        }
        {
            int kk = tid >> 4, c4 = tid & 15;
            *(float4*)&sB[kk][4*c4] = *(const float4*)&Wo[(size_t)(k0+kk)*DD + 4*c4];
        }
        __syncthreads();
#pragma unroll
        for (int kk = 0; kk < 16; kk++) {
            float4 a = *(float4*)&sA[kk][ty*4];
            float4 b = *(float4*)&sB[kk][tx*4];
            float av[4] = {a.x,a.y,a.z,a.w};
            float bv[4] = {b.x,b.y,b.z,b.w};
#pragma unroll
            for (int i = 0; i < 4; i++)
#pragma unroll
                for (int j = 0; j < 4; j++)
                    acc[i][j] = fmaf(av[i], bv[j], acc[i][j]);
        }
        __syncthreads();
    }
    float4 bias = *(const float4*)&bo[tx*4];
    float bv[4] = {bias.x, bias.y, bias.z, bias.w};
#pragma unroll
    for (int i = 0; i < 4; i++) {
        int row = row0 + ty*4 + i;
        float4 v = make_float4(acc[i][0]+bv[0], acc[i][1]+bv[1],
                               acc[i][2]+bv[2], acc[i][3]+bv[3]);
        *(float4*)&out[(size_t)row * DD + tx*4] = v;
    }
}

// ---------------------------------------------------------------------------
extern "C" void kernel_launch(void* const* d_in, const int* in_sizes, int n_in,
                              void* d_out, int out_size)
{
    const float* x  = (const float*)d_in[0];
    const float* Wq = (const float*)d_in[1];
    const float* Wk = (const float*)d_in[2];
    const float* Wv = (const float*)d_in[3];
    const float* Wo = (const float*)d_in[4];
    const float* bo = (const float*)d_in[5];
    float* out = (float*)d_out;

    const long NTD = (long)NBB * TT * DD;
    float* attn = out + NTD;

    int smem_s = 4 * 128 * QS * (int)sizeof(__nv_bfloat16);  // 73728
    cudaFuncSetAttribute(sgemm_tc_kernel, cudaFuncAttributeMaxDynamicSharedMemorySize, smem_s);

    cvt_x_kernel<<<3072, 256>>>(x);
    cvt_w_kernel<<<dim3(576, 3), 256>>>(Wq, Wk, Wv);
    qkv_tc_kernel<<<dim3(32, 36), 256>>>();
    cvt_qkv_kernel<<<dim3(3072, 3), 256>>>();
    sgemm_tc_kernel<<<dim3(36, NBH), 256, smem_s>>>(attn);
    softmax_kernel<<<dim3(128, NBH), 256>>>(attn);
    pv_tc_kernel<<<dim3(8, NBH), 256>>>(attn);
    oproj_kernel<<<64, 256>>>(Wo, bo, out);
}

// round 10
// speedup vs baseline: 1.7005x; 1.0603x over previous
#include <cuda_runtime.h>
#include <cuda_bf16.h>
#include <mma.h>
#include <cstdint>
#include <math.h>

using namespace nvcuda;

#define HN   12
#define TT   1024
#define DD   64
#define DINE 768
#define NBB  4
#define NTR  (NBB*TT)   // 4096
#define NBH  (NBB*HN)   // 48

// Scratch (static device globals — allocation-free)
__device__ float g_o[NTR*DINE];
__device__ __nv_bfloat16 g_x_hi[NTR*DINE];
__device__ __nv_bfloat16 g_x_lo[NTR*DINE];
__device__ __nv_bfloat16 g_w_hi[36*DINE*DD];   // [mh][k][n]
__device__ __nv_bfloat16 g_w_lo[36*DINE*DD];
__device__ __nv_bfloat16 g_qh[NBH*TT*DD], g_ql[NBH*TT*DD];
__device__ __nv_bfloat16 g_kh[NBH*TT*DD], g_kl[NBH*TT*DD];
__device__ __nv_bfloat16 g_vh[NBH*TT*DD], g_vl[NBH*TT*DD];

// Fast exp on the FMA pipe. x <= 0 expected (handles -inf via clamp).
__device__ __forceinline__ float fexp(float x) {
    x = fmaxf(x, -87.0f);
    float y = x * 1.44269504088896f;
    int   n = __float2int_rn(y);
    float f = y - (float)n;
    float p = 1.53989348e-4f;
    p = fmaf(p, f, 1.33336246e-3f);
    p = fmaf(p, f, 9.61812910e-3f);
    p = fmaf(p, f, 5.55041087e-2f);
    p = fmaf(p, f, 2.40226507e-1f);
    p = fmaf(p, f, 6.93147181e-1f);
    p = fmaf(p, f, 1.0f);
    return p * __int_as_float((n + 127) << 23);
}

// ---------------------------------------------------------------------------
// Convert X -> bf16 hi/lo
// ---------------------------------------------------------------------------
__global__ __launch_bounds__(256) void cvt_x_kernel(const float* __restrict__ x)
{
    int i = blockIdx.x * 256 + threadIdx.x;      // float4 index
    float4 v = ((const float4*)x)[i];
    __nv_bfloat162 h0 = __floats2bfloat162_rn(v.x, v.y);
    __nv_bfloat162 h1 = __floats2bfloat162_rn(v.z, v.w);
    float2 f0 = __bfloat1622float2(h0);
    float2 f1 = __bfloat1622float2(h1);
    __nv_bfloat162 l0 = __floats2bfloat162_rn(v.x - f0.x, v.y - f0.y);
    __nv_bfloat162 l1 = __floats2bfloat162_rn(v.z - f1.x, v.w - f1.y);
    ((__nv_bfloat162*)g_x_hi)[2*i]   = h0;
    ((__nv_bfloat162*)g_x_hi)[2*i+1] = h1;
    ((__nv_bfloat162*)g_x_lo)[2*i]   = l0;
    ((__nv_bfloat162*)g_x_lo)[2*i+1] = l1;
}

// ---------------------------------------------------------------------------
// Convert W -> bf16 hi/lo, native [h][k][n]
// ---------------------------------------------------------------------------
__global__ __launch_bounds__(256) void cvt_w_kernel(
    const float* __restrict__ Wq, const float* __restrict__ Wk,
    const float* __restrict__ Wv)
{
    int mat = blockIdx.y;
    const float* Wm = (mat == 0 ? Wq : mat == 1 ? Wk : Wv);
    size_t base = (size_t)mat * HN * DINE * DD;
    int i = blockIdx.x * 256 + threadIdx.x;
    float4 v = ((const float4*)Wm)[i];
    __nv_bfloat162 h0 = __floats2bfloat162_rn(v.x, v.y);
    __nv_bfloat162 h1 = __floats2bfloat162_rn(v.z, v.w);
    float2 f0 = __bfloat1622float2(h0);
    float2 f1 = __bfloat1622float2(h1);
    __nv_bfloat162 l0 = __floats2bfloat162_rn(v.x - f0.x, v.y - f0.y);
    __nv_bfloat162 l1 = __floats2bfloat162_rn(v.z - f1.x, v.w - f1.y);
    ((__nv_bfloat162*)(g_w_hi + base))[2*i]   = h0;
    ((__nv_bfloat162*)(g_w_hi + base))[2*i+1] = h1;
    ((__nv_bfloat162*)(g_w_lo + base))[2*i]   = l0;
    ((__nv_bfloat162*)(g_w_lo + base))[2*i+1] = l1;
}

// ---------------------------------------------------------------------------
// QKV via WMMA bf16 hi/lo split. K-chunk = 64. Epilogue emits bf16 hi/lo
// Q/K/V directly (no fp32 round-trip).
// ---------------------------------------------------------------------------
#define ASTR 72
#define BSTR 72
#define CSTR 68
// dyn smem: bf16 tiles 2*(128+64)*72*2B = 55296B ; fp32 epi buf 128*68*4 = 34816B
#define QKV_SMEM 55296

__global__ __launch_bounds__(256) void qkv_tc_kernel()
{
    extern __shared__ __align__(16) char dyn[];
    __nv_bfloat16* sAh = (__nv_bfloat16*)dyn;                    // 128*ASTR
    __nv_bfloat16* sAl = sAh + 128*ASTR;
    __nv_bfloat16* sBh = sAl + 128*ASTR;                         // 64*BSTR
    __nv_bfloat16* sBl = sBh + 64*BSTR;
    float* sC = (float*)dyn;                                     // epilogue reuse

    int rt = blockIdx.x, mh = blockIdx.y;
    int row0 = rt * 128;
    int tid = threadIdx.x, warp = tid >> 5;
    int wm = warp & 3, wn = warp >> 2;

    wmma::fragment<wmma::accumulator, 16, 16, 16, float> c[2][2];
#pragma unroll
    for (int mi = 0; mi < 2; mi++)
#pragma unroll
        for (int ni = 0; ni < 2; ni++) wmma::fill_fragment(c[mi][ni], 0.0f);

    for (int k0 = 0; k0 < DINE; k0 += 64) {
        // A: 128x64 hi+lo (1024 uint4 each)
#pragma unroll
        for (int it = 0; it < 4; it++) {
            int idx = tid + 256 * it;
            int r = idx >> 3, cc = (idx & 7) * 8;
            size_t src = (size_t)(row0 + r) * DINE + k0 + cc;
            *(uint4*)&sAh[r*ASTR + cc] = *(const uint4*)&g_x_hi[src];
            *(uint4*)&sAl[r*ASTR + cc] = *(const uint4*)&g_x_lo[src];
        }
        // B: 64x64 hi+lo (512 uint4 each)
#pragma unroll
        for (int it = 0; it < 2; it++) {
            int idx = tid + 256 * it;
            int r = idx >> 3, cc = (idx & 7) * 8;
            size_t src = ((size_t)mh * DINE + (k0 + r)) * DD + cc;
            *(uint4*)&sBh[r*BSTR + cc] = *(const uint4*)&g_w_hi[src];
            *(uint4*)&sBl[r*BSTR + cc] = *(const uint4*)&g_w_lo[src];
        }
        __syncthreads();

#pragma unroll
        for (int ks = 0; ks < 64; ks += 16) {
            wmma::fragment<wmma::matrix_a, 16, 16, 16, __nv_bfloat16, wmma::row_major> ah[2], al[2];
            wmma::fragment<wmma::matrix_b, 16, 16, 16, __nv_bfloat16, wmma::row_major> bh[2], bl[2];
#pragma unroll
            for (int mi = 0; mi < 2; mi++) {
                wmma::load_matrix_sync(ah[mi], &sAh[(wm*32 + mi*16)*ASTR + ks], ASTR);
                wmma::load_matrix_sync(al[mi], &sAl[(wm*32 + mi*16)*ASTR + ks], ASTR);
            }
#pragma unroll
            for (int ni = 0; ni < 2; ni++) {
                wmma::load_matrix_sync(bh[ni], &sBh[ks*BSTR + wn*32 + ni*16], BSTR);
                wmma::load_matrix_sync(bl[ni], &sBl[ks*BSTR + wn*32 + ni*16], BSTR);
            }
#pragma unroll
            for (int mi = 0; mi < 2; mi++)
#pragma unroll
                for (int ni = 0; ni < 2; ni++) {
                    wmma::mma_sync(c[mi][ni], ah[mi], bh[ni], c[mi][ni]);
                    wmma::mma_sync(c[mi][ni], ah[mi], bl[ni], c[mi][ni]);
                    wmma::mma_sync(c[mi][ni], al[mi], bh[ni], c[mi][ni]);
                }
        }
        __syncthreads();
    }

    // Epilogue: frags -> smem fp32 -> bf16 hi/lo gmem
#pragma unroll
    for (int mi = 0; mi < 2; mi++)
#pragma unroll
        for (int ni = 0; ni < 2; ni++)
            wmma::store_matrix_sync(&sC[(wm*32 + mi*16)*CSTR + wn*32 + ni*16],
                                    c[mi][ni], CSTR, wmma::mem_row_major);
    __syncthreads();

    int mat = mh / HN, h = mh % HN;
    __nv_bfloat16* dh = (mat == 0 ? g_qh : mat == 1 ? g_kh : g_vh);
    __nv_bfloat16* dl = (mat == 0 ? g_ql : mat == 1 ? g_kl : g_vl);
    int n = row0 >> 10, t0 = row0 & (TT - 1);
    size_t base = ((size_t)(n*HN + h)*TT + t0) * DD;
#pragma unroll
    for (int it = 0; it < 4; it++) {
        int idx = tid + 256 * it;
        int r = idx >> 3, d0 = (idx & 7) * 8;
        const float* src = &sC[r*CSTR + d0];
        __nv_bfloat162 hh[4], ll[4];
#pragma unroll
        for (int q = 0; q < 4; q++) {
            float a = src[2*q], b = src[2*q+1];
            hh[q] = __floats2bfloat162_rn(a, b);
            float2 f = __bfloat1622float2(hh[q]);
            ll[q] = __floats2bfloat162_rn(a - f.x, b - f.y);
        }
        *(uint4*)&dh[base + (size_t)r*DD + d0] = *(uint4*)hh;
        *(uint4*)&dl[base + (size_t)r*DD + d0] = *(uint4*)ll;
    }
}

// ---------------------------------------------------------------------------
// S = Q @ K^T via WMMA bf16 split, per (bh, lower-tri 128x128 block).
// ---------------------------------------------------------------------------
#define QS 72
__global__ __launch_bounds__(256) void sgemm_tc_kernel(float* __restrict__ attn)
{
    extern __shared__ __nv_bfloat16 smb[];
    __nv_bfloat16* sQh = smb;
    __nv_bfloat16* sQl = smb + 128*QS;
    __nv_bfloat16* sKh = smb + 2*128*QS;
    __nv_bfloat16* sKl = smb + 3*128*QS;

    int idx = blockIdx.x, rb = 0;
    while (idx > rb) { idx -= rb + 1; rb++; }
    int cb = idx;
    int bh = blockIdx.y;

    const __nv_bfloat16* qh = g_qh + ((size_t)bh * TT + rb*128) * DD;
    const __nv_bfloat16* ql = g_ql + ((size_t)bh * TT + rb*128) * DD;
    const __nv_bfloat16* kh = g_kh + ((size_t)bh * TT + cb*128) * DD;
    const __nv_bfloat16* kl = g_kl + ((size_t)bh * TT + cb*128) * DD;

    int tid = threadIdx.x, warp = tid >> 5;
    int wm = warp & 3, wn = warp >> 2;

#pragma unroll
    for (int it = 0; it < 4; it++) {
        int v = tid + 256 * it;
        int r = v >> 3, cc = (v & 7) * 8;
        *(uint4*)&sQh[r*QS + cc] = *(const uint4*)&qh[(size_t)r*DD + cc];
        *(uint4*)&sQl[r*QS + cc] = *(const uint4*)&ql[(size_t)r*DD + cc];
        *(uint4*)&sKh[r*QS + cc] = *(const uint4*)&kh[(size_t)r*DD + cc];
        *(uint4*)&sKl[r*QS + cc] = *(const uint4*)&kl[(size_t)r*DD + cc];
    }
    __syncthreads();

    wmma::fragment<wmma::accumulator, 16, 16, 16, float> c[2][4];
#pragma unroll
    for (int mi = 0; mi < 2; mi++)
#pragma unroll
        for (int ni = 0; ni < 4; ni++) wmma::fill_fragment(c[mi][ni], 0.0f);

#pragma unroll
    for (int k0 = 0; k0 < 64; k0 += 16) {
        wmma::fragment<wmma::matrix_a, 16, 16, 16, __nv_bfloat16, wmma::row_major> ah[2], al[2];
#pragma unroll
        for (int mi = 0; mi < 2; mi++) {
            wmma::load_matrix_sync(ah[mi], &sQh[(wm*32 + mi*16)*QS + k0], QS);
            wmma::load_matrix_sync(al[mi], &sQl[(wm*32 + mi*16)*QS + k0], QS);
        }
#pragma unroll
        for (int ni = 0; ni < 4; ni++) {
            wmma::fragment<wmma::matrix_b, 16, 16, 16, __nv_bfloat16, wmma::col_major> bh, bl;
            wmma::load_matrix_sync(bh, &sKh[(wn*64 + ni*16)*QS + k0], QS);
            wmma::load_matrix_sync(bl, &sKl[(wn*64 + ni*16)*QS + k0], QS);
#pragma unroll
            for (int mi = 0; mi < 2; mi++) {
                wmma::mma_sync(c[mi][ni], ah[mi], bh, c[mi][ni]);
                wmma::mma_sync(c[mi][ni], ah[mi], bl, c[mi][ni]);
                wmma::mma_sync(c[mi][ni], al[mi], bh, c[mi][ni]);
            }
        }
    }

#pragma unroll
    for (int mi = 0; mi < 2; mi++)
#pragma unroll
        for (int ni = 0; ni < 4; ni++) {
            int row = rb*128 + wm*32 + mi*16;
            int col = cb*128 + wn*64 + ni*16;
            wmma::store_matrix_sync(&attn[((size_t)bh*TT + row)*TT + col],
                                    c[mi][ni], TT, wmma::mem_row_major);
        }
}

// ---------------------------------------------------------------------------
// Softmax (causal + "==0 -> -inf"), one warp/row, float4, dead-block skip.
// ---------------------------------------------------------------------------
__global__ __launch_bounds__(256) void softmax_kernel(float* __restrict__ attn)
{
    int tid = threadIdx.x, lane = tid & 31, warp = tid >> 5;
    int tq = blockIdx.x * 8 + warp;
    int bh = blockIdx.y;
    float* row = attn + ((size_t)bh * TT + tq) * TT;
    int len = tq + 1;
    int jlim = (len + 127) >> 7;          // live 128-col blocks

    float4 pv4[8];
    float mx = -INFINITY;
#pragma unroll
    for (int j = 0; j < 8; j++) {
        if (j < jlim) {
            int base = j*128 + lane*4;
            float4 v = *(const float4*)&row[base];
            float* e = &v.x;
#pragma unroll
            for (int cq = 0; cq < 4; cq++) {
                float val = (base + cq < len) ? (e[cq] == 0.0f ? -INFINITY : e[cq])
                                              : -INFINITY;
                e[cq] = val;
                mx = fmaxf(mx, val);
            }
            pv4[j] = v;
        } else {
            pv4[j] = make_float4(0.f, 0.f, 0.f, 0.f);
        }
    }
#pragma unroll
    for (int o = 16; o > 0; o >>= 1) mx = fmaxf(mx, __shfl_xor_sync(0xffffffffu, mx, o));

    float sum = 0.f;
#pragma unroll
    for (int j = 0; j < 8; j++) {
        if (j < jlim) {
            int base = j*128 + lane*4;
            float* e = &pv4[j].x;
#pragma unroll
            for (int cq = 0; cq < 4; cq++) {
                float p = (base + cq < len) ? fexp(e[cq] - mx) : 0.0f;
                e[cq] = p;
                sum += p;
            }
        }
    }
#pragma unroll
    for (int o = 16; o > 0; o >>= 1) sum += __shfl_xor_sync(0xffffffffu, sum, o);
    float inv = 1.f / sum;

#pragma unroll
    for (int j = 0; j < 8; j++) {
        float4 v = pv4[j];
        v.x *= inv; v.y *= inv; v.z *= inv; v.w *= inv;
        *(float4*)&row[j*128 + lane*4] = v;
    }
}

// ---------------------------------------------------------------------------
// O = P @ V via WMMA: P fp32->bf16 hi/lo in-kernel; V bf16 hi/lo.
// ---------------------------------------------------------------------------
#define PS 40
#define VS 72
__global__ __launch_bounds__(256) void pv_tc_kernel(const float* __restrict__ attn)
{
    __shared__ __align__(32) __nv_bfloat16 sPh[128*PS], sPl[128*PS];
    __shared__ __align__(32) __nv_bfloat16 sVh[32*VS],  sVl[32*VS];

    int rb = 7 - blockIdx.x;
    int bh = blockIdx.y;
    int row0 = rb * 128;
    int kmax = (rb + 1) * 128;
    const float* pp = attn + ((size_t)bh * TT + row0) * TT;
    const __nv_bfloat16* vh = g_vh + (size_t)bh * TT * DD;
    const __nv_bfloat16* vl = g_vl + (size_t)bh * TT * DD;

    int tid = threadIdx.x, warp = tid >> 5;
    int wm = warp & 3, wn = warp >> 2;

    wmma::fragment<wmma::accumulator, 16, 16, 16, float> c[2][2];
#pragma unroll
    for (int mi = 0; mi < 2; mi++)
#pragma unroll
        for (int ni = 0; ni < 2; ni++) wmma::fill_fragment(c[mi][ni], 0.0f);

    for (int sb = 0; sb < kmax; sb += 32) {
#pragma unroll
        for (int it = 0; it < 4; it++) {
            int v = tid + 256 * it;
            int r = v >> 3, c4 = (v & 7) * 4;
            float4 p = *(const float4*)&pp[(size_t)r * TT + sb + c4];
            __nv_bfloat162 h0 = __floats2bfloat162_rn(p.x, p.y);
            __nv_bfloat162 h1 = __floats2bfloat162_rn(p.z, p.w);
            float2 f0 = __bfloat1622float2(h0);
            float2 f1 = __bfloat1622float2(h1);
            __nv_bfloat162 l0 = __floats2bfloat162_rn(p.x - f0.x, p.y - f0.y);
            __nv_bfloat162 l1 = __floats2bfloat162_rn(p.z - f1.x, p.w - f1.y);
            *(__nv_bfloat162*)&sPh[r*PS + c4]     = h0;
            *(__nv_bfloat162*)&sPh[r*PS + c4 + 2] = h1;
            *(__nv_bfloat162*)&sPl[r*PS + c4]     = l0;
            *(__nv_bfloat162*)&sPl[r*PS + c4 + 2] = l1;
        }
        {
            int r = tid >> 3, cc = (tid & 7) * 8;
            *(uint4*)&sVh[r*VS + cc] = *(const uint4*)&vh[(size_t)(sb + r)*DD + cc];
            *(uint4*)&sVl[r*VS + cc] = *(const uint4*)&vl[(size_t)(sb + r)*DD + cc];
        }
        __syncthreads();

#pragma unroll
        for (int k0 = 0; k0 < 32; k0 += 16) {
            wmma::fragment<wmma::matrix_a, 16, 16, 16, __nv_bfloat16, wmma::row_major> ah[2], al[2];
#pragma unroll
            for (int mi = 0; mi < 2; mi++) {
                wmma::load_matrix_sync(ah[mi], &sPh[(wm*32 + mi*16)*PS + k0], PS);
                wmma::load_matrix_sync(al[mi], &sPl[(wm*32 + mi*16)*PS + k0], PS);
            }
#pragma unroll
            for (int ni = 0; ni < 2; ni++) {
                wmma::fragment<wmma::matrix_b, 16, 16, 16, __nv_bfloat16, wmma::row_major> bh, bl;
                wmma::load_matrix_sync(bh, &sVh[k0*VS + wn*32 + ni*16], VS);
                wmma::load_matrix_sync(bl, &sVl[k0*VS + wn*32 + ni*16], VS);
#pragma unroll
                for (int mi = 0; mi < 2; mi++) {
                    wmma::mma_sync(c[mi][ni], ah[mi], bh, c[mi][ni]);
                    wmma::mma_sync(c[mi][ni], ah[mi], bl, c[mi][ni]);
                    wmma::mma_sync(c[mi][ni], al[mi], bh, c[mi][ni]);
                }
            }
        }
        __syncthreads();
    }

    int n = bh / HN, h = bh % HN;
#pragma unroll
    for (int mi = 0; mi < 2; mi++)
#pragma unroll
        for (int ni = 0; ni < 2; ni++) {
            int t = row0 + wm*32 + mi*16;
            wmma::store_matrix_sync(
                &g_o[((size_t)(n*TT + t))*DINE + h*DD + wn*32 + ni*16],
                c[mi][ni], DINE, wmma::mem_row_major);
        }
}

// ---------------------------------------------------------------------------
// Output projection: out[4096,64] = g_o[4096,768] @ Wo[768,64] + bo
// ---------------------------------------------------------------------------
__global__ __launch_bounds__(256) void oproj_kernel(
    const float* __restrict__ Wo, const float* __restrict__ bo,
    float* __restrict__ out)
{
    int row0 = blockIdx.x * 64;
    __shared__ float sA[16][64];
    __shared__ float sB[16][64];
    int tid = threadIdx.x, tx = tid & 15, ty = tid >> 4;

    float acc[4][4];
#pragma unroll
    for (int i = 0; i < 4; i++)
#pragma unroll
        for (int j = 0; j < 4; j++) acc[i][j] = 0.f;

    for (int k0 = 0; k0 < DINE; k0 += 16) {
        {
            int r = tid >> 2, kq = tid & 3;
            float4 a = *(const float4*)&g_o[(size_t)(row0 + r) * DINE + k0 + 4 * kq];
            sA[4*kq+0][r] = a.x; sA[4*kq+1][r] = a.y;
            sA[4*kq+2][r] = a.z; sA[4*kq+3][r] = a.w;
        }
        {
            int kk = tid >> 4, c4 = tid & 15;
            *(float4*)&sB[kk][4*c4] = *(const float4*)&Wo[(size_t)(k0+kk)*DD + 4*c4];
        }
        __syncthreads();
#pragma unroll
        for (int kk = 0; kk < 16; kk++) {
            float4 a = *(float4*)&sA[kk][ty*4];
            float4 b = *(float4*)&sB[kk][tx*4];
            float av[4] = {a.x,a.y,a.z,a.w};
            float bv[4] = {b.x,b.y,b.z,b.w};
#pragma unroll
            for (int i = 0; i < 4; i++)
#pragma unroll
                for (int j = 0; j < 4; j++)
                    acc[i][j] = fmaf(av[i], bv[j], acc[i][j]);
        }
        __syncthreads();
    }
    float4 bias = *(const float4*)&bo[tx*4];
    float bv[4] = {bias.x, bias.y, bias.z, bias.w};
#pragma unroll
    for (int i = 0; i < 4; i++) {
        int row = row0 + ty*4 + i;
        float4 v = make_float4(acc[i][0]+bv[0], acc[i][1]+bv[1],
                               acc[i][2]+bv[2], acc[i][3]+bv[3]);
        *(float4*)&out[(size_t)row * DD + tx*4] = v;
    }
}

// ---------------------------------------------------------------------------
extern "C" void kernel_launch(void* const* d_in, const int* in_sizes, int n_in,
                              void* d_out, int out_size)
{
    const float* x  = (const float*)d_in[0];
    const float* Wq = (const float*)d_in[1];
    const float* Wk = (const float*)d_in[2];
    const float* Wv = (const float*)d_in[3];
    const float* Wo = (const float*)d_in[4];
    const float* bo = (const float*)d_in[5];
    float* out = (float*)d_out;

    const long NTD = (long)NBB * TT * DD;
    float* attn = out + NTD;

    cudaFuncSetAttribute(qkv_tc_kernel, cudaFuncAttributeMaxDynamicSharedMemorySize, QKV_SMEM);
    int smem_s = 4 * 128 * QS * (int)sizeof(__nv_bfloat16);  // 73728
    cudaFuncSetAttribute(sgemm_tc_kernel, cudaFuncAttributeMaxDynamicSharedMemorySize, smem_s);

    cvt_x_kernel<<<3072, 256>>>(x);
    cvt_w_kernel<<<dim3(576, 3), 256>>>(Wq, Wk, Wv);
    qkv_tc_kernel<<<dim3(32, 36), 256, QKV_SMEM>>>();
    sgemm_tc_kernel<<<dim3(36, NBH), 256, smem_s>>>(attn);
    softmax_kernel<<<dim3(128, NBH), 256>>>(attn);
    pv_tc_kernel<<<dim3(8, NBH), 256>>>(attn);
    oproj_kernel<<<64, 256>>>(Wo, bo, out);
}

// round 11
// speedup vs baseline: 2.1534x; 1.2663x over previous
#include <cuda_runtime.h>
#include <cuda_bf16.h>
#include <mma.h>
#include <cstdint>
#include <math.h>

using namespace nvcuda;

#define HN   12
#define TT   1024
#define DD   64
#define DINE 768
#define NBB  4
#define NTR  (NBB*TT)   // 4096
#define NBH  (NBB*HN)   // 48

// Scratch (static device globals — allocation-free)
__device__ __nv_bfloat16 g_x_hi[NTR*DINE];
__device__ __nv_bfloat16 g_x_lo[NTR*DINE];
__device__ __nv_bfloat16 g_w_hi[36*DINE*DD];   // [mh][k][n]
__device__ __nv_bfloat16 g_w_lo[36*DINE*DD];
__device__ __nv_bfloat16 g_wo_h[DINE*DD], g_wo_l[DINE*DD];
__device__ __nv_bfloat16 g_qh[NBH*TT*DD], g_ql[NBH*TT*DD];
__device__ __nv_bfloat16 g_kh[NBH*TT*DD], g_kl[NBH*TT*DD];
__device__ __nv_bfloat16 g_vh[NBH*TT*DD], g_vl[NBH*TT*DD];
__device__ __nv_bfloat16 g_oh[NTR*DINE], g_ol[NTR*DINE];

// Fast exp on the FMA pipe. x <= 0 expected (handles -inf via clamp).
__device__ __forceinline__ float fexp(float x) {
    x = fmaxf(x, -87.0f);
    float y = x * 1.44269504088896f;
    int   n = __float2int_rn(y);
    float f = y - (float)n;
    float p = 1.53989348e-4f;
    p = fmaf(p, f, 1.33336246e-3f);
    p = fmaf(p, f, 9.61812910e-3f);
    p = fmaf(p, f, 5.55041087e-2f);
    p = fmaf(p, f, 2.40226507e-1f);
    p = fmaf(p, f, 6.93147181e-1f);
    p = fmaf(p, f, 1.0f);
    return p * __int_as_float((n + 127) << 23);
}

__device__ __forceinline__ void split4(float4 v, __nv_bfloat162* hh, __nv_bfloat162* ll) {
    hh[0] = __floats2bfloat162_rn(v.x, v.y);
    hh[1] = __floats2bfloat162_rn(v.z, v.w);
    float2 f0 = __bfloat1622float2(hh[0]);
    float2 f1 = __bfloat1622float2(hh[1]);
    ll[0] = __floats2bfloat162_rn(v.x - f0.x, v.y - f0.y);
    ll[1] = __floats2bfloat162_rn(v.z - f1.x, v.w - f1.y);
}

// ---------------------------------------------------------------------------
// Converters
// ---------------------------------------------------------------------------
__global__ __launch_bounds__(256) void cvt_x_kernel(const float* __restrict__ x)
{
    int i = blockIdx.x * 256 + threadIdx.x;
    float4 v = ((const float4*)x)[i];
    __nv_bfloat162 hh[2], ll[2];
    split4(v, hh, ll);
    ((__nv_bfloat162*)g_x_hi)[2*i]   = hh[0];
    ((__nv_bfloat162*)g_x_hi)[2*i+1] = hh[1];
    ((__nv_bfloat162*)g_x_lo)[2*i]   = ll[0];
    ((__nv_bfloat162*)g_x_lo)[2*i+1] = ll[1];
}

__global__ __launch_bounds__(256) void cvt_w_kernel(
    const float* __restrict__ Wq, const float* __restrict__ Wk,
    const float* __restrict__ Wv)
{
    int mat = blockIdx.y;
    const float* Wm = (mat == 0 ? Wq : mat == 1 ? Wk : Wv);
    size_t base = (size_t)mat * HN * DINE * DD;
    int i = blockIdx.x * 256 + threadIdx.x;
    float4 v = ((const float4*)Wm)[i];
    __nv_bfloat162 hh[2], ll[2];
    split4(v, hh, ll);
    ((__nv_bfloat162*)(g_w_hi + base))[2*i]   = hh[0];
    ((__nv_bfloat162*)(g_w_hi + base))[2*i+1] = hh[1];
    ((__nv_bfloat162*)(g_w_lo + base))[2*i]   = ll[0];
    ((__nv_bfloat162*)(g_w_lo + base))[2*i+1] = ll[1];
}

__global__ __launch_bounds__(256) void cvt_wo_kernel(const float* __restrict__ Wo)
{
    int i = blockIdx.x * 256 + threadIdx.x;   // 12288 float4
    float4 v = ((const float4*)Wo)[i];
    __nv_bfloat162 hh[2], ll[2];
    split4(v, hh, ll);
    ((__nv_bfloat162*)g_wo_h)[2*i]   = hh[0];
    ((__nv_bfloat162*)g_wo_h)[2*i+1] = hh[1];
    ((__nv_bfloat162*)g_wo_l)[2*i]   = ll[0];
    ((__nv_bfloat162*)g_wo_l)[2*i+1] = ll[1];
}

// ---------------------------------------------------------------------------
// QKV via WMMA bf16 split: 2 heads per CTA. grid (32, 18).
// C[128, 128] per CTA; epilogue -> bf16 hi/lo Q/K/V.
// ---------------------------------------------------------------------------
#define ASTR 72
#define BSTR2 136
#define QKV_SMEM 71680   // A 2*128*72*2 + B 2*64*136*2; epi fp32 128*132*4=67584 fits

__global__ __launch_bounds__(256) void qkv_tc_kernel()
{
    extern __shared__ __align__(16) char dyn[];
    __nv_bfloat16* sAh = (__nv_bfloat16*)dyn;              // 128*ASTR
    __nv_bfloat16* sAl = sAh + 128*ASTR;
    __nv_bfloat16* sBh = sAl + 128*ASTR;                   // 64*BSTR2
    __nv_bfloat16* sBl = sBh + 64*BSTR2;
    float* sC = (float*)dyn;                               // epi: 128 x 132

    int rt = blockIdx.x;                  // 128-row tile
    int cbk = blockIdx.y;                 // 0..17
    int mat = cbk / 6, hp = cbk % 6, h0 = 2 * hp;
    int row0 = rt * 128;
    int tid = threadIdx.x, warp = tid >> 5;
    int wm = warp & 3, wn = warp >> 2;    // warp tile 32 rows x 64 cols

    wmma::fragment<wmma::accumulator, 16, 16, 16, float> c[2][4];
#pragma unroll
    for (int mi = 0; mi < 2; mi++)
#pragma unroll
        for (int ni = 0; ni < 4; ni++) wmma::fill_fragment(c[mi][ni], 0.0f);

    for (int k0 = 0; k0 < DINE; k0 += 64) {
        // A: 128x64 hi+lo
#pragma unroll
        for (int it = 0; it < 4; it++) {
            int idx = tid + 256 * it;
            int r = idx >> 3, cc = (idx & 7) * 8;
            size_t src = (size_t)(row0 + r) * DINE + k0 + cc;
            *(uint4*)&sAh[r*ASTR + cc] = *(const uint4*)&g_x_hi[src];
            *(uint4*)&sAl[r*ASTR + cc] = *(const uint4*)&g_x_lo[src];
        }
        // B: 64k x 128cols (2 heads) hi+lo
#pragma unroll
        for (int it = 0; it < 4; it++) {
            int idx = tid + 256 * it;
            int r = idx >> 4, c8 = (idx & 15) * 8;
            int mh = mat * HN + h0 + (c8 >> 6);
            int d0 = c8 & 63;
            size_t src = ((size_t)mh * DINE + (k0 + r)) * DD + d0;
            *(uint4*)&sBh[r*BSTR2 + c8] = *(const uint4*)&g_w_hi[src];
            *(uint4*)&sBl[r*BSTR2 + c8] = *(const uint4*)&g_w_lo[src];
        }
        __syncthreads();

#pragma unroll
        for (int ks = 0; ks < 64; ks += 16) {
            wmma::fragment<wmma::matrix_a, 16, 16, 16, __nv_bfloat16, wmma::row_major> ah[2], al[2];
#pragma unroll
            for (int mi = 0; mi < 2; mi++) {
                wmma::load_matrix_sync(ah[mi], &sAh[(wm*32 + mi*16)*ASTR + ks], ASTR);
                wmma::load_matrix_sync(al[mi], &sAl[(wm*32 + mi*16)*ASTR + ks], ASTR);
            }
#pragma unroll
            for (int ni = 0; ni < 4; ni++) {
                wmma::fragment<wmma::matrix_b, 16, 16, 16, __nv_bfloat16, wmma::row_major> bh, bl;
                wmma::load_matrix_sync(bh, &sBh[ks*BSTR2 + wn*64 + ni*16], BSTR2);
                wmma::load_matrix_sync(bl, &sBl[ks*BSTR2 + wn*64 + ni*16], BSTR2);
#pragma unroll
                for (int mi = 0; mi < 2; mi++) {
                    wmma::mma_sync(c[mi][ni], ah[mi], bh, c[mi][ni]);
                    wmma::mma_sync(c[mi][ni], ah[mi], bl, c[mi][ni]);
                    wmma::mma_sync(c[mi][ni], al[mi], bh, c[mi][ni]);
                }
            }
        }
        __syncthreads();
    }

    // Epilogue: frags -> smem fp32 -> bf16 hi/lo gmem (2 heads)
#pragma unroll
    for (int mi = 0; mi < 2; mi++)
#pragma unroll
        for (int ni = 0; ni < 4; ni++)
            wmma::store_matrix_sync(&sC[(wm*32 + mi*16)*132 + wn*64 + ni*16],
                                    c[mi][ni], 132, wmma::mem_row_major);
    __syncthreads();

    __nv_bfloat16* dh = (mat == 0 ? g_qh : mat == 1 ? g_kh : g_vh);
    __nv_bfloat16* dl = (mat == 0 ? g_ql : mat == 1 ? g_kl : g_vl);
    int n = row0 >> 10, t0 = row0 & (TT - 1);
#pragma unroll
    for (int it = 0; it < 8; it++) {
        int idx = tid + 256 * it;
        int r = idx >> 4, c8 = (idx & 15) * 8;
        int h = h0 + (c8 >> 6), d0 = c8 & 63;
        size_t base = ((size_t)(n*HN + h)*TT + t0 + r) * DD + d0;
        const float* src = &sC[r*132 + c8];
        __nv_bfloat162 hh[4], ll[4];
#pragma unroll
        for (int q = 0; q < 2; q++) {
            float4 v = *(const float4*)&src[4*q];
            split4(v, &hh[2*q], &ll[2*q]);
        }
        *(uint4*)&dh[base] = *(uint4*)hh;
        *(uint4*)&dl[base] = *(uint4*)ll;
    }
}

// ---------------------------------------------------------------------------
// S = Q @ K^T via WMMA bf16 split, per (bh, lower-tri 128x128 block).
// ---------------------------------------------------------------------------
#define QS 72
__global__ __launch_bounds__(256) void sgemm_tc_kernel(float* __restrict__ attn)
{
    extern __shared__ __nv_bfloat16 smb[];
    __nv_bfloat16* sQh = smb;
    __nv_bfloat16* sQl = smb + 128*QS;
    __nv_bfloat16* sKh = smb + 2*128*QS;
    __nv_bfloat16* sKl = smb + 3*128*QS;

    int idx = blockIdx.x, rb = 0;
    while (idx > rb) { idx -= rb + 1; rb++; }
    int cb = idx;
    int bh = blockIdx.y;

    const __nv_bfloat16* qh = g_qh + ((size_t)bh * TT + rb*128) * DD;
    const __nv_bfloat16* ql = g_ql + ((size_t)bh * TT + rb*128) * DD;
    const __nv_bfloat16* kh = g_kh + ((size_t)bh * TT + cb*128) * DD;
    const __nv_bfloat16* kl = g_kl + ((size_t)bh * TT + cb*128) * DD;

    int tid = threadIdx.x, warp = tid >> 5;
    int wm = warp & 3, wn = warp >> 2;

#pragma unroll
    for (int it = 0; it < 4; it++) {
        int v = tid + 256 * it;
        int r = v >> 3, cc = (v & 7) * 8;
        *(uint4*)&sQh[r*QS + cc] = *(const uint4*)&qh[(size_t)r*DD + cc];
        *(uint4*)&sQl[r*QS + cc] = *(const uint4*)&ql[(size_t)r*DD + cc];
        *(uint4*)&sKh[r*QS + cc] = *(const uint4*)&kh[(size_t)r*DD + cc];
        *(uint4*)&sKl[r*QS + cc] = *(const uint4*)&kl[(size_t)r*DD + cc];
    }
    __syncthreads();

    wmma::fragment<wmma::accumulator, 16, 16, 16, float> c[2][4];
#pragma unroll
    for (int mi = 0; mi < 2; mi++)
#pragma unroll
        for (int ni = 0; ni < 4; ni++) wmma::fill_fragment(c[mi][ni], 0.0f);

#pragma unroll
    for (int k0 = 0; k0 < 64; k0 += 16) {
        wmma::fragment<wmma::matrix_a, 16, 16, 16, __nv_bfloat16, wmma::row_major> ah[2], al[2];
#pragma unroll
        for (int mi = 0; mi < 2; mi++) {
            wmma::load_matrix_sync(ah[mi], &sQh[(wm*32 + mi*16)*QS + k0], QS);
            wmma::load_matrix_sync(al[mi], &sQl[(wm*32 + mi*16)*QS + k0], QS);
        }
#pragma unroll
        for (int ni = 0; ni < 4; ni++) {
            wmma::fragment<wmma::matrix_b, 16, 16, 16, __nv_bfloat16, wmma::col_major> bh, bl;
            wmma::load_matrix_sync(bh, &sKh[(wn*64 + ni*16)*QS + k0], QS);
            wmma::load_matrix_sync(bl, &sKl[(wn*64 + ni*16)*QS + k0], QS);
#pragma unroll
            for (int mi = 0; mi < 2; mi++) {
                wmma::mma_sync(c[mi][ni], ah[mi], bh, c[mi][ni]);
                wmma::mma_sync(c[mi][ni], ah[mi], bl, c[mi][ni]);
                wmma::mma_sync(c[mi][ni], al[mi], bh, c[mi][ni]);
            }
        }
    }

#pragma unroll
    for (int mi = 0; mi < 2; mi++)
#pragma unroll
        for (int ni = 0; ni < 4; ni++) {
            int row = rb*128 + wm*32 + mi*16;
            int col = cb*128 + wn*64 + ni*16;
            wmma::store_matrix_sync(&attn[((size_t)bh*TT + row)*TT + col],
                                    c[mi][ni], TT, wmma::mem_row_major);
        }
}

// ---------------------------------------------------------------------------
// Softmax (causal + "==0 -> -inf"), one warp/row, float4, dead-block skip.
// ---------------------------------------------------------------------------
__global__ __launch_bounds__(256) void softmax_kernel(float* __restrict__ attn)
{
    int tid = threadIdx.x, lane = tid & 31, warp = tid >> 5;
    int tq = blockIdx.x * 8 + warp;
    int bh = blockIdx.y;
    float* row = attn + ((size_t)bh * TT + tq) * TT;
    int len = tq + 1;
    int jlim = (len + 127) >> 7;

    float4 pv4[8];
    float mx = -INFINITY;
#pragma unroll
    for (int j = 0; j < 8; j++) {
        if (j < jlim) {
            int base = j*128 + lane*4;
            float4 v = *(const float4*)&row[base];
            float* e = &v.x;
#pragma unroll
            for (int cq = 0; cq < 4; cq++) {
                float val = (base + cq < len) ? (e[cq] == 0.0f ? -INFINITY : e[cq])
                                              : -INFINITY;
                e[cq] = val;
                mx = fmaxf(mx, val);
            }
            pv4[j] = v;
        } else {
            pv4[j] = make_float4(0.f, 0.f, 0.f, 0.f);
        }
    }
#pragma unroll
    for (int o = 16; o > 0; o >>= 1) mx = fmaxf(mx, __shfl_xor_sync(0xffffffffu, mx, o));

    float sum = 0.f;
#pragma unroll
    for (int j = 0; j < 8; j++) {
        if (j < jlim) {
            int base = j*128 + lane*4;
            float* e = &pv4[j].x;
#pragma unroll
            for (int cq = 0; cq < 4; cq++) {
                float p = (base + cq < len) ? fexp(e[cq] - mx) : 0.0f;
                e[cq] = p;
                sum += p;
            }
        }
    }
#pragma unroll
    for (int o = 16; o > 0; o >>= 1) sum += __shfl_xor_sync(0xffffffffu, sum, o);
    float inv = 1.f / sum;

#pragma unroll
    for (int j = 0; j < 8; j++) {
        float4 v = pv4[j];
        v.x *= inv; v.y *= inv; v.z *= inv; v.w *= inv;
        *(float4*)&row[j*128 + lane*4] = v;
    }
}

// ---------------------------------------------------------------------------
// O = P @ V via WMMA, key-chunk 64. Epilogue writes bf16 hi/lo O.
// ---------------------------------------------------------------------------
#define PVS 72
#define PV_SMEM 55296   // P 2*128*72*2 + V 2*64*72*2; epi 128*68*4=34816 fits

__global__ __launch_bounds__(256) void pv_tc_kernel(const float* __restrict__ attn)
{
    extern __shared__ __align__(16) char dynp[];
    __nv_bfloat16* sPh = (__nv_bfloat16*)dynp;           // 128*PVS
    __nv_bfloat16* sPl = sPh + 128*PVS;
    __nv_bfloat16* sVh = sPl + 128*PVS;                  // 64*PVS
    __nv_bfloat16* sVl = sVh + 64*PVS;
    float* sC = (float*)dynp;                            // epi: 128 x 68

    int rb = 7 - blockIdx.x;
    int bh = blockIdx.y;
    int row0 = rb * 128;
    int kmax = (rb + 1) * 128;
    const float* pp = attn + ((size_t)bh * TT + row0) * TT;
    const __nv_bfloat16* vh = g_vh + (size_t)bh * TT * DD;
    const __nv_bfloat16* vl = g_vl + (size_t)bh * TT * DD;

    int tid = threadIdx.x, warp = tid >> 5;
    int wm = warp & 3, wn = warp >> 2;

    wmma::fragment<wmma::accumulator, 16, 16, 16, float> c[2][2];
#pragma unroll
    for (int mi = 0; mi < 2; mi++)
#pragma unroll
        for (int ni = 0; ni < 2; ni++) wmma::fill_fragment(c[mi][ni], 0.0f);

    for (int sb = 0; sb < kmax; sb += 64) {
        // P chunk 128x64 fp32 -> bf16 hi/lo
#pragma unroll
        for (int it = 0; it < 8; it++) {
            int v = tid + 256 * it;
            int r = v >> 4, c4 = (v & 15) * 4;
            float4 p = *(const float4*)&pp[(size_t)r * TT + sb + c4];
            __nv_bfloat162 hh[2], ll[2];
            split4(p, hh, ll);
            *(__nv_bfloat162*)&sPh[r*PVS + c4]     = hh[0];
            *(__nv_bfloat162*)&sPh[r*PVS + c4 + 2] = hh[1];
            *(__nv_bfloat162*)&sPl[r*PVS + c4]     = ll[0];
            *(__nv_bfloat162*)&sPl[r*PVS + c4 + 2] = ll[1];
        }
        // V chunk 64x64 hi/lo
#pragma unroll
        for (int it = 0; it < 2; it++) {
            int v = tid + 256 * it;
            int r = v >> 3, cc = (v & 7) * 8;
            *(uint4*)&sVh[r*PVS + cc] = *(const uint4*)&vh[(size_t)(sb + r)*DD + cc];
            *(uint4*)&sVl[r*PVS + cc] = *(const uint4*)&vl[(size_t)(sb + r)*DD + cc];
        }
        __syncthreads();

#pragma unroll
        for (int k0 = 0; k0 < 64; k0 += 16) {
            wmma::fragment<wmma::matrix_a, 16, 16, 16, __nv_bfloat16, wmma::row_major> ah[2], al[2];
#pragma unroll
            for (int mi = 0; mi < 2; mi++) {
                wmma::load_matrix_sync(ah[mi], &sPh[(wm*32 + mi*16)*PVS + k0], PVS);
                wmma::load_matrix_sync(al[mi], &sPl[(wm*32 + mi*16)*PVS + k0], PVS);
            }
#pragma unroll
            for (int ni = 0; ni < 2; ni++) {
                wmma::fragment<wmma::matrix_b, 16, 16, 16, __nv_bfloat16, wmma::row_major> bh, bl;
                wmma::load_matrix_sync(bh, &sVh[k0*PVS + wn*32 + ni*16], PVS);
                wmma::load_matrix_sync(bl, &sVl[k0*PVS + wn*32 + ni*16], PVS);
#pragma unroll
                for (int mi = 0; mi < 2; mi++) {
                    wmma::mma_sync(c[mi][ni], ah[mi], bh, c[mi][ni]);
                    wmma::mma_sync(c[mi][ni], ah[mi], bl, c[mi][ni]);
                    wmma::mma_sync(c[mi][ni], al[mi], bh, c[mi][ni]);
                }
            }
        }
        __syncthreads();
    }

    // Epilogue: frags -> smem fp32 -> bf16 hi/lo O
#pragma unroll
    for (int mi = 0; mi < 2; mi++)
#pragma unroll
        for (int ni = 0; ni < 2; ni++)
            wmma::store_matrix_sync(&sC[(wm*32 + mi*16)*68 + wn*32 + ni*16],
                                    c[mi][ni], 68, wmma::mem_row_major);
    __syncthreads();

    int n = bh / HN, h = bh % HN;
#pragma unroll
    for (int it = 0; it < 4; it++) {
        int idx = tid + 256 * it;
        int r = idx >> 3, d0 = (idx & 7) * 8;
        size_t base = ((size_t)(n*TT + row0 + r))*DINE + h*DD + d0;
        const float* src = &sC[r*68 + d0];
        __nv_bfloat162 hh[4], ll[4];
#pragma unroll
        for (int q = 0; q < 2; q++) {
            float4 v = *(const float4*)&src[4*q];
            split4(v, &hh[2*q], &ll[2*q]);
        }
        *(uint4*)&g_oh[base] = *(uint4*)hh;
        *(uint4*)&g_ol[base] = *(uint4*)ll;
    }
}

// ---------------------------------------------------------------------------
// Output projection via WMMA: out = O @ Wo + bo. grid 128 x 32 rows.
// ---------------------------------------------------------------------------
#define OP_SMEM 27648   // A 2*32*72*2 + B 2*64*72*2; epi 32*68*4=8704 fits

__global__ __launch_bounds__(256) void oproj_tc_kernel(
    const float* __restrict__ bo, float* __restrict__ out)
{
    extern __shared__ __align__(16) char dyno[];
    __nv_bfloat16* sAh = (__nv_bfloat16*)dyno;           // 32*PVS
    __nv_bfloat16* sAl = sAh + 32*PVS;
    __nv_bfloat16* sBh = sAl + 32*PVS;                   // 64*PVS
    __nv_bfloat16* sBl = sBh + 64*PVS;
    float* sC = (float*)dyno;                            // epi: 32 x 68

    int row0 = blockIdx.x * 32;
    int tid = threadIdx.x, warp = tid >> 5;
    int wm = warp & 1, wn = warp >> 1;   // warp tile 16x16

    wmma::fragment<wmma::accumulator, 16, 16, 16, float> c;
    wmma::fill_fragment(c, 0.0f);

    for (int k0 = 0; k0 < DINE; k0 += 64) {
        {
            int r = tid >> 3, cc = (tid & 7) * 8;      // 32x64: 256 uint4
            size_t src = (size_t)(row0 + r) * DINE + k0 + cc;
            *(uint4*)&sAh[r*PVS + cc] = *(const uint4*)&g_oh[src];
            *(uint4*)&sAl[r*PVS + cc] = *(const uint4*)&g_ol[src];
        }
#pragma unroll
        for (int it = 0; it < 2; it++) {
            int idx = tid + 256 * it;
            int r = idx >> 3, cc = (idx & 7) * 8;      // 64x64: 512 uint4
            size_t src = (size_t)(k0 + r) * DD + cc;
            *(uint4*)&sBh[r*PVS + cc] = *(const uint4*)&g_wo_h[src];
            *(uint4*)&sBl[r*PVS + cc] = *(const uint4*)&g_wo_l[src];
        }
        __syncthreads();

#pragma unroll
        for (int ks = 0; ks < 64; ks += 16) {
            wmma::fragment<wmma::matrix_a, 16, 16, 16, __nv_bfloat16, wmma::row_major> ah, al;
            wmma::fragment<wmma::matrix_b, 16, 16, 16, __nv_bfloat16, wmma::row_major> bh, bl;
            wmma::load_matrix_sync(ah, &sAh[(wm*16)*PVS + ks], PVS);
            wmma::load_matrix_sync(al, &sAl[(wm*16)*PVS + ks], PVS);
            wmma::load_matrix_sync(bh, &sBh[ks*PVS + wn*16], PVS);
            wmma::load_matrix_sync(bl, &sBl[ks*PVS + wn*16], PVS);
            wmma::mma_sync(c, ah, bh, c);
            wmma::mma_sync(c, ah, bl, c);
            wmma::mma_sync(c, al, bh, c);
        }
        __syncthreads();
    }

    wmma::store_matrix_sync(&sC[(wm*16)*68 + wn*16], c, 68, wmma::mem_row_major);
    __syncthreads();

#pragma unroll
    for (int it = 0; it < 2; it++) {
        int idx = tid + 256 * it;
        int r = idx >> 4, c4 = (idx & 15) * 4;
        float4 b = *(const float4*)&bo[c4];
        const float* src = &sC[r*68 + c4];
        float4 v = make_float4(src[0]+b.x, src[1]+b.y, src[2]+b.z, src[3]+b.w);
        *(float4*)&out[(size_t)(row0 + r) * DD + c4] = v;
    }
}

// ---------------------------------------------------------------------------
extern "C" void kernel_launch(void* const* d_in, const int* in_sizes, int n_in,
                              void* d_out, int out_size)
{
    const float* x  = (const float*)d_in[0];
    const float* Wq = (const float*)d_in[1];
    const float* Wk = (const float*)d_in[2];
    const float* Wv = (const float*)d_in[3];
    const float* Wo = (const float*)d_in[4];
    const float* bo = (const float*)d_in[5];
    float* out = (float*)d_out;

    const long NTD = (long)NBB * TT * DD;
    float* attn = out + NTD;

    cudaFuncSetAttribute(qkv_tc_kernel, cudaFuncAttributeMaxDynamicSharedMemorySize, QKV_SMEM);
    int smem_s = 4 * 128 * QS * (int)sizeof(__nv_bfloat16);  // 73728
    cudaFuncSetAttribute(sgemm_tc_kernel, cudaFuncAttributeMaxDynamicSharedMemorySize, smem_s);
    cudaFuncSetAttribute(pv_tc_kernel, cudaFuncAttributeMaxDynamicSharedMemorySize, PV_SMEM);
    cudaFuncSetAttribute(oproj_tc_kernel, cudaFuncAttributeMaxDynamicSharedMemorySize, OP_SMEM);

    cvt_x_kernel<<<3072, 256>>>(x);
    cvt_w_kernel<<<dim3(576, 3), 256>>>(Wq, Wk, Wv);
    cvt_wo_kernel<<<48, 256>>>(Wo);
    qkv_tc_kernel<<<dim3(32, 18), 256, QKV_SMEM>>>();
    sgemm_tc_kernel<<<dim3(36, NBH), 256, smem_s>>>(attn);
    softmax_kernel<<<dim3(128, NBH), 256>>>(attn);
    pv_tc_kernel<<<dim3(8, NBH), 256, PV_SMEM>>>(attn);
    oproj_tc_kernel<<<128, 256, OP_SMEM>>>(bo, out);
}